// round 1
// baseline (speedup 1.0000x reference)
#include <cuda_runtime.h>
#include <cuda_bf16.h>

#define BB 64
#define SS 512
#define EE 512
#define HD 1024
#define NO 10
#define GRU_BLOCKS 128
#define GRU_THREADS 256

// -------- scratch (static device globals; no allocation) --------
__device__ float g_xproj[(size_t)SS * BB * 3 * HD]; // [s][b][3072] = Xproj + bias
__device__ float g_H[2][HD * BB];                   // k-major: [k][b]
__device__ float g_Hr[HD * BB];                     // k-major: [k][b]  (H * r)
__device__ float g_Z[BB * HD];                      // [b][col]
__device__ unsigned g_count = 0;
__device__ unsigned g_gen = 0;

// -------- f32x2 packed math helpers (sm_103a) --------
__device__ __forceinline__ unsigned long long ffma2(unsigned long long a,
                                                    unsigned long long b,
                                                    unsigned long long c) {
    unsigned long long d;
    asm("fma.rn.f32x2 %0, %1, %2, %3;" : "=l"(d) : "l"(a), "l"(b), "l"(c));
    return d;
}
__device__ __forceinline__ unsigned long long pack2(float lo, float hi) {
    unsigned long long r;
    asm("mov.b64 %0, {%1,%2};" : "=l"(r) : "f"(lo), "f"(hi));
    return r;
}
__device__ __forceinline__ float2 unpack2(unsigned long long v) {
    float2 f;
    asm("mov.b64 {%0,%1}, %2;" : "=f"(f.x), "=f"(f.y) : "l"(v));
    return f;
}
__device__ __forceinline__ float sigmoidf_(float x) {
    return 1.0f / (1.0f + __expf(-x));
}

// -------- grid barrier (sense-reversing, all blocks resident) --------
__device__ __forceinline__ void grid_barrier() {
    __syncthreads();
    if (threadIdx.x == 0) {
        __threadfence();
        unsigned gen = *(volatile unsigned*)&g_gen;
        if (atomicAdd(&g_count, 1u) == GRU_BLOCKS - 1) {
            *(volatile unsigned*)&g_count = 0u;
            __threadfence();
            *(volatile unsigned*)&g_gen = gen + 1u;
        } else {
            while (*(volatile unsigned*)&g_gen == gen) __nanosleep(32);
        }
        __threadfence();
    }
    __syncthreads();
}

// =====================================================================
// Kernel 1: input projection  Xproj[s][b][j] = emb[tok(b,s)] @ Wx_g + b_g
// grid = (48 n-tiles, 512 s), 256 threads, BM=64(=one s), BN=64, BK=16
// =====================================================================
__global__ __launch_bounds__(256) void proj_kernel(
    const int* __restrict__ inputs, const float* __restrict__ emb,
    const float* __restrict__ Wxr, const float* __restrict__ Wxz,
    const float* __restrict__ Wxc, const float* __restrict__ br,
    const float* __restrict__ bz, const float* __restrict__ bc) {
    const int s  = blockIdx.y;   // 0..511 (m-tile: rows are b=0..63)
    const int nt = blockIdx.x;   // 0..47
    const int gate = nt >> 4;    // 16 n-tiles per gate
    const float* Wx   = (gate == 0) ? Wxr : ((gate == 1) ? Wxz : Wxc);
    const float* bias = (gate == 0) ? br  : ((gate == 1) ? bz  : bc);
    const int col0 = (nt & 15) * 64;  // column within gate [0,1024)

    __shared__ int tok[64];
    __shared__ __align__(16) float As[16][68];  // [k][m], padded
    __shared__ __align__(16) float Bs[16][64];  // [k][n]

    const int tid = threadIdx.x;
    if (tid < 64) tok[tid] = inputs[tid * SS + s];
    __syncthreads();

    const int tx = tid & 15, ty = tid >> 4;
    const int n0 = tx * 4, m0 = ty * 4;
    unsigned long long acc[4][2];
#pragma unroll
    for (int i = 0; i < 4; i++) { acc[i][0] = 0ull; acc[i][1] = 0ull; }

    const int lm = tid >> 2, lkq = tid & 3;    // A staging map
    const int bk = tid >> 4, bnq = tid & 15;   // B staging map

#pragma unroll 1
    for (int k0 = 0; k0 < EE; k0 += 16) {
        float4 av = *(const float4*)(emb + (size_t)tok[lm] * EE + k0 + lkq * 4);
        float4 bv = *(const float4*)(Wx + (size_t)(k0 + bk) * HD + col0 + bnq * 4);
        __syncthreads();
        As[lkq * 4 + 0][lm] = av.x;
        As[lkq * 4 + 1][lm] = av.y;
        As[lkq * 4 + 2][lm] = av.z;
        As[lkq * 4 + 3][lm] = av.w;
        *(float4*)&Bs[bk][bnq * 4] = bv;
        __syncthreads();
#pragma unroll
        for (int kk = 0; kk < 16; ++kk) {
            float4 a4 = *(const float4*)&As[kk][m0];
            ulonglong2 b2 = *(const ulonglong2*)&Bs[kk][n0];
            unsigned long long aa;
            aa = pack2(a4.x, a4.x);
            acc[0][0] = ffma2(aa, b2.x, acc[0][0]);
            acc[0][1] = ffma2(aa, b2.y, acc[0][1]);
            aa = pack2(a4.y, a4.y);
            acc[1][0] = ffma2(aa, b2.x, acc[1][0]);
            acc[1][1] = ffma2(aa, b2.y, acc[1][1]);
            aa = pack2(a4.z, a4.z);
            acc[2][0] = ffma2(aa, b2.x, acc[2][0]);
            acc[2][1] = ffma2(aa, b2.y, acc[2][1]);
            aa = pack2(a4.w, a4.w);
            acc[3][0] = ffma2(aa, b2.x, acc[3][0]);
            acc[3][1] = ffma2(aa, b2.y, acc[3][1]);
        }
    }
    float4 bi = *(const float4*)(bias + col0 + n0);
#pragma unroll
    for (int i = 0; i < 4; i++) {
        float2 lo = unpack2(acc[i][0]), hi = unpack2(acc[i][1]);
        float4 v = make_float4(lo.x + bi.x, lo.y + bi.y, hi.x + bi.z, hi.y + bi.w);
        *(float4*)(g_xproj + ((size_t)s * BB + m0 + i) * (3 * HD) + gate * HD + col0 + n0) = v;
    }
}

// =====================================================================
// Kernel 2: persistent GRU. grid=128 blocks x 256 threads, 512 steps.
// Phase 1: r,z = sigmoid(H @ [Whr|Whz] + Xproj_rz). 16 cols/block.
// Phase 2: h = tanh((H*r) @ Whc + Xproj_c); H' = z*H + (1-z)*h. 8 cols/block.
// =====================================================================
__global__ __launch_bounds__(GRU_THREADS, 1) void gru_kernel(
    const float* __restrict__ Whr, const float* __restrict__ Whz,
    const float* __restrict__ Whc) {
    __shared__ __align__(16) float Hs[4096];  // 64 k x 64 b staging
    const int tid = threadIdx.x;
    const int bx  = blockIdx.x;

    // zero-init H0 (must happen every launch: graph replays)
    {
        int idx = bx * GRU_THREADS + tid;  // 0..32767
        if (idx < 16384) ((float4*)g_H[0])[idx] = make_float4(0.f, 0.f, 0.f, 0.f);
    }
    grid_barrier();

    const int m  = tid >> 2;        // batch row 0..63
    const int cq = tid & 3;         // column quad
    const int jbase = bx * 16;      // rz-space column base 0..2047
    const int gate1 = jbase >> 10;  // 0 = r, 1 = z
    const float* W1 = gate1 ? Whz : Whr;
    const int col1 = (jbase & 1023) + cq * 4;  // 4 cols (gate-local)
    const int c2 = bx * 8 + cq * 2;            // phase-2: 2 cols

    int p = 0;
#pragma unroll 1
    for (int s = 0; s < SS; ++s) {
        const float* Hcur = g_H[p];
        float* Hnext = g_H[p ^ 1];

        // ---------------- phase 1: r and z ----------------
        unsigned long long acc0 = 0ull, acc1 = 0ull;
#pragma unroll 1
        for (int kc = 0; kc < HD; kc += 64) {
            __syncthreads();
            for (int i = tid; i < 1024; i += GRU_THREADS)
                ((float4*)Hs)[i] = ((const float4*)(Hcur + kc * 64))[i];
            __syncthreads();
#pragma unroll 8
            for (int kk = 0; kk < 64; ++kk) {
                float h = Hs[kk * 64 + m];
                unsigned long long hh = pack2(h, h);
                ulonglong2 w = *(const ulonglong2*)(W1 + (size_t)(kc + kk) * HD + col1);
                acc0 = ffma2(hh, w.x, acc0);
                acc1 = ffma2(hh, w.y, acc1);
            }
        }
        {
            float2 a0 = unpack2(acc0), a1 = unpack2(acc1);
            const float4 xp = *(const float4*)(g_xproj + ((size_t)s * BB + m) * (3 * HD) +
                                               gate1 * HD + col1);
            float v0 = sigmoidf_(a0.x + xp.x);
            float v1 = sigmoidf_(a0.y + xp.y);
            float v2 = sigmoidf_(a1.x + xp.z);
            float v3 = sigmoidf_(a1.y + xp.w);
            if (gate1 == 0) {  // r -> Hr = H * r  (k-major store)
                g_Hr[(col1 + 0) * BB + m] = Hcur[(col1 + 0) * BB + m] * v0;
                g_Hr[(col1 + 1) * BB + m] = Hcur[(col1 + 1) * BB + m] * v1;
                g_Hr[(col1 + 2) * BB + m] = Hcur[(col1 + 2) * BB + m] * v2;
                g_Hr[(col1 + 3) * BB + m] = Hcur[(col1 + 3) * BB + m] * v3;
            } else {           // z
                *(float4*)(g_Z + m * HD + col1) = make_float4(v0, v1, v2, v3);
            }
        }
        grid_barrier();

        // ---------------- phase 2: h + combine ----------------
        unsigned long long acc = 0ull;
#pragma unroll 1
        for (int kc = 0; kc < HD; kc += 64) {
            __syncthreads();
            for (int i = tid; i < 1024; i += GRU_THREADS)
                ((float4*)Hs)[i] = ((const float4*)(g_Hr + kc * 64))[i];
            __syncthreads();
#pragma unroll 8
            for (int kk = 0; kk < 64; ++kk) {
                float h = Hs[kk * 64 + m];
                unsigned long long hh = pack2(h, h);
                unsigned long long w = *(const unsigned long long*)(Whc + (size_t)(kc + kk) * HD + c2);
                acc = ffma2(hh, w, acc);
            }
        }
        {
            float2 a = unpack2(acc);
            const float2 xp = *(const float2*)(g_xproj + ((size_t)s * BB + m) * (3 * HD) +
                                               2 * HD + c2);
            float h0 = tanhf(a.x + xp.x);
            float h1 = tanhf(a.y + xp.y);
            float2 z2 = *(const float2*)(g_Z + m * HD + c2);
            float H0 = Hcur[(c2 + 0) * BB + m];
            float H1 = Hcur[(c2 + 1) * BB + m];
            Hnext[(c2 + 0) * BB + m] = z2.x * H0 + (1.0f - z2.x) * h0;
            Hnext[(c2 + 1) * BB + m] = z2.y * H1 + (1.0f - z2.y) * h1;
        }
        grid_barrier();
        p ^= 1;
    }
    // after 512 steps (even), final H lives in g_H[0]
}

// =====================================================================
// Kernel 3: logits + softmax. grid=64 (one block per batch row).
// =====================================================================
__global__ __launch_bounds__(128) void out_kernel(const float* __restrict__ Whq,
                                                  const float* __restrict__ bq,
                                                  float* __restrict__ out) {
    const int b = blockIdx.x;
    const int t = threadIdx.x;  // 128 threads
    float acc[NO];
#pragma unroll
    for (int o = 0; o < NO; o++) acc[o] = 0.f;
    for (int k = t; k < HD; k += 128) {
        float hv = g_H[0][k * BB + b];
        const float* w = Whq + (size_t)k * NO;
#pragma unroll
        for (int o = 0; o < NO; o++) acc[o] += hv * w[o];
    }
    __shared__ float part[128 * NO];
#pragma unroll
    for (int o = 0; o < NO; o++) part[t * NO + o] = acc[o];
    __syncthreads();
    __shared__ float logits[NO];
    if (t < NO) {
        float sum = bq[t];
        for (int i = 0; i < 128; i++) sum += part[i * NO + t];
        logits[t] = sum;
    }
    __syncthreads();
    if (t == 0) {
        float mx = logits[0];
#pragma unroll
        for (int o = 1; o < NO; o++) mx = fmaxf(mx, logits[o]);
        float e[NO];
        float sum = 0.f;
#pragma unroll
        for (int o = 0; o < NO; o++) { e[o] = __expf(logits[o] - mx); sum += e[o]; }
        float inv = 1.0f / sum;
#pragma unroll
        for (int o = 0; o < NO; o++) out[b * NO + o] = e[o] * inv;
    }
}

// =====================================================================
extern "C" void kernel_launch(void* const* d_in, const int* in_sizes, int n_in,
                              void* d_out, int out_size) {
    const int*   inputs = (const int*)d_in[0];
    const float* emb    = (const float*)d_in[1];
    const float* Wxr = (const float*)d_in[2];
    const float* Whr = (const float*)d_in[3];
    const float* br  = (const float*)d_in[4];
    const float* Wxz = (const float*)d_in[5];
    const float* Whz = (const float*)d_in[6];
    const float* bz  = (const float*)d_in[7];
    const float* Wxc = (const float*)d_in[8];
    const float* Whc = (const float*)d_in[9];
    const float* bc  = (const float*)d_in[10];
    const float* Whq = (const float*)d_in[11];
    const float* bq  = (const float*)d_in[12];
    float* out = (float*)d_out;

    dim3 pg(48, 512);
    proj_kernel<<<pg, 256>>>(inputs, emb, Wxr, Wxz, Wxc, br, bz, bc);
    gru_kernel<<<GRU_BLOCKS, GRU_THREADS>>>(Whr, Whz, Whc);
    out_kernel<<<64, 128>>>(Whq, bq, out);
}

// round 2
// speedup vs baseline: 1.0040x; 1.0040x over previous
#include <cuda_runtime.h>
#include <cuda_bf16.h>

#define BB 64
#define SS 512
#define EE 512
#define HD 1024
#define NO 10
#define GRU_BLOCKS 128
#define GRU_THREADS 256

// -------- scratch (static device globals; no allocation) --------
__device__ float g_xproj[(size_t)SS * BB * 3 * HD]; // [s][b][3072] = Xproj + bias
__device__ float g_H[2][HD * BB];                   // k-major: [k][b]
__device__ float g_Hr[HD * BB];                     // k-major: [k][b]  (H * r)
__device__ float g_Z[BB * HD];                      // [b][col]
__device__ unsigned g_count = 0;
__device__ unsigned g_gen = 0;

// -------- f32x2 packed math helpers (sm_103a) --------
__device__ __forceinline__ unsigned long long ffma2(unsigned long long a,
                                                    unsigned long long b,
                                                    unsigned long long c) {
    unsigned long long d;
    asm("fma.rn.f32x2 %0, %1, %2, %3;" : "=l"(d) : "l"(a), "l"(b), "l"(c));
    return d;
}
__device__ __forceinline__ unsigned long long pack2(float lo, float hi) {
    unsigned long long r;
    asm("mov.b64 %0, {%1,%2};" : "=l"(r) : "f"(lo), "f"(hi));
    return r;
}
__device__ __forceinline__ float2 unpack2(unsigned long long v) {
    float2 f;
    asm("mov.b64 {%0,%1}, %2;" : "=f"(f.x), "=f"(f.y) : "l"(v));
    return f;
}
__device__ __forceinline__ float sigmoidf_(float x) {
    return 1.0f / (1.0f + __expf(-x));
}

// -------- grid barrier (sense-reversing, all blocks resident) --------
__device__ __forceinline__ void grid_barrier() {
    __syncthreads();
    if (threadIdx.x == 0) {
        __threadfence();
        unsigned gen = *(volatile unsigned*)&g_gen;
        if (atomicAdd(&g_count, 1u) == GRU_BLOCKS - 1) {
            *(volatile unsigned*)&g_count = 0u;
            __threadfence();
            *(volatile unsigned*)&g_gen = gen + 1u;
        } else {
            while (*(volatile unsigned*)&g_gen == gen) __nanosleep(32);
        }
        __threadfence();
    }
    __syncthreads();
}

// =====================================================================
// Kernel 1: input projection  Xproj[s][b][j] = emb[tok(b,s)] @ Wx_g + b_g
// grid = (48 n-tiles, 512 s), 256 threads, BM=64(=one s), BN=64, BK=16
// =====================================================================
__global__ __launch_bounds__(256) void proj_kernel(
    const int* __restrict__ inputs, const float* __restrict__ emb,
    const float* __restrict__ Wxr, const float* __restrict__ Wxz,
    const float* __restrict__ Wxc, const float* __restrict__ br,
    const float* __restrict__ bz, const float* __restrict__ bc) {
    const int s  = blockIdx.y;   // 0..511 (m-tile: rows are b=0..63)
    const int nt = blockIdx.x;   // 0..47
    const int gate = nt >> 4;    // 16 n-tiles per gate
    const float* Wx   = (gate == 0) ? Wxr : ((gate == 1) ? Wxz : Wxc);
    const float* bias = (gate == 0) ? br  : ((gate == 1) ? bz  : bc);
    const int col0 = (nt & 15) * 64;  // column within gate [0,1024)

    __shared__ int tok[64];
    __shared__ __align__(16) float As[16][68];  // [k][m], padded
    __shared__ __align__(16) float Bs[16][64];  // [k][n]

    const int tid = threadIdx.x;
    if (tid < 64) tok[tid] = inputs[tid * SS + s];
    __syncthreads();

    const int tx = tid & 15, ty = tid >> 4;
    const int n0 = tx * 4, m0 = ty * 4;
    unsigned long long acc[4][2];
#pragma unroll
    for (int i = 0; i < 4; i++) { acc[i][0] = 0ull; acc[i][1] = 0ull; }

    const int lm = tid >> 2, lkq = tid & 3;    // A staging map
    const int bk = tid >> 4, bnq = tid & 15;   // B staging map

#pragma unroll 1
    for (int k0 = 0; k0 < EE; k0 += 16) {
        float4 av = *(const float4*)(emb + (size_t)tok[lm] * EE + k0 + lkq * 4);
        float4 bv = *(const float4*)(Wx + (size_t)(k0 + bk) * HD + col0 + bnq * 4);
        __syncthreads();
        As[lkq * 4 + 0][lm] = av.x;
        As[lkq * 4 + 1][lm] = av.y;
        As[lkq * 4 + 2][lm] = av.z;
        As[lkq * 4 + 3][lm] = av.w;
        *(float4*)&Bs[bk][bnq * 4] = bv;
        __syncthreads();
#pragma unroll
        for (int kk = 0; kk < 16; ++kk) {
            float4 a4 = *(const float4*)&As[kk][m0];
            ulonglong2 b2 = *(const ulonglong2*)&Bs[kk][n0];
            unsigned long long aa;
            aa = pack2(a4.x, a4.x);
            acc[0][0] = ffma2(aa, b2.x, acc[0][0]);
            acc[0][1] = ffma2(aa, b2.y, acc[0][1]);
            aa = pack2(a4.y, a4.y);
            acc[1][0] = ffma2(aa, b2.x, acc[1][0]);
            acc[1][1] = ffma2(aa, b2.y, acc[1][1]);
            aa = pack2(a4.z, a4.z);
            acc[2][0] = ffma2(aa, b2.x, acc[2][0]);
            acc[2][1] = ffma2(aa, b2.y, acc[2][1]);
            aa = pack2(a4.w, a4.w);
            acc[3][0] = ffma2(aa, b2.x, acc[3][0]);
            acc[3][1] = ffma2(aa, b2.y, acc[3][1]);
        }
    }
    float4 bi = *(const float4*)(bias + col0 + n0);
#pragma unroll
    for (int i = 0; i < 4; i++) {
        float2 lo = unpack2(acc[i][0]), hi = unpack2(acc[i][1]);
        float4 v = make_float4(lo.x + bi.x, lo.y + bi.y, hi.x + bi.z, hi.y + bi.w);
        *(float4*)(g_xproj + ((size_t)s * BB + m0 + i) * (3 * HD) + gate * HD + col0 + n0) = v;
    }
}

// =====================================================================
// Kernel 2: persistent GRU. grid=128 blocks x 256 threads, 512 steps.
// Phase 1: r,z = sigmoid(H @ [Whr|Whz] + Xproj_rz). 16 cols/block.
// Phase 2: h = tanh((H*r) @ Whc + Xproj_c); H' = z*H + (1-z)*h. 8 cols/block.
// =====================================================================
__global__ __launch_bounds__(GRU_THREADS, 1) void gru_kernel(
    const float* __restrict__ Whr, const float* __restrict__ Whz,
    const float* __restrict__ Whc) {
    __shared__ __align__(16) float Hs[4096];  // 64 k x 64 b staging
    const int tid = threadIdx.x;
    const int bx  = blockIdx.x;

    // zero-init H0 (must happen every launch: graph replays)
    {
        int idx = bx * GRU_THREADS + tid;  // 0..32767
        if (idx < 16384) ((float4*)g_H[0])[idx] = make_float4(0.f, 0.f, 0.f, 0.f);
    }
    grid_barrier();

    const int m  = tid >> 2;        // batch row 0..63
    const int cq = tid & 3;         // column quad
    const int jbase = bx * 16;      // rz-space column base 0..2047
    const int gate1 = jbase >> 10;  // 0 = r, 1 = z
    const float* W1 = gate1 ? Whz : Whr;
    const int col1 = (jbase & 1023) + cq * 4;  // 4 cols (gate-local)
    const int c2 = bx * 8 + cq * 2;            // phase-2: 2 cols

    int p = 0;
#pragma unroll 1
    for (int s = 0; s < SS; ++s) {
        const float* Hcur = g_H[p];
        float* Hnext = g_H[p ^ 1];

        // ---------------- phase 1: r and z ----------------
        unsigned long long acc0 = 0ull, acc1 = 0ull;
#pragma unroll 1
        for (int kc = 0; kc < HD; kc += 64) {
            __syncthreads();
            for (int i = tid; i < 1024; i += GRU_THREADS)
                ((float4*)Hs)[i] = ((const float4*)(Hcur + kc * 64))[i];
            __syncthreads();
#pragma unroll 8
            for (int kk = 0; kk < 64; ++kk) {
                float h = Hs[kk * 64 + m];
                unsigned long long hh = pack2(h, h);
                ulonglong2 w = *(const ulonglong2*)(W1 + (size_t)(kc + kk) * HD + col1);
                acc0 = ffma2(hh, w.x, acc0);
                acc1 = ffma2(hh, w.y, acc1);
            }
        }
        {
            float2 a0 = unpack2(acc0), a1 = unpack2(acc1);
            const float4 xp = *(const float4*)(g_xproj + ((size_t)s * BB + m) * (3 * HD) +
                                               gate1 * HD + col1);
            float v0 = sigmoidf_(a0.x + xp.x);
            float v1 = sigmoidf_(a0.y + xp.y);
            float v2 = sigmoidf_(a1.x + xp.z);
            float v3 = sigmoidf_(a1.y + xp.w);
            if (gate1 == 0) {  // r -> Hr = H * r  (k-major store)
                g_Hr[(col1 + 0) * BB + m] = Hcur[(col1 + 0) * BB + m] * v0;
                g_Hr[(col1 + 1) * BB + m] = Hcur[(col1 + 1) * BB + m] * v1;
                g_Hr[(col1 + 2) * BB + m] = Hcur[(col1 + 2) * BB + m] * v2;
                g_Hr[(col1 + 3) * BB + m] = Hcur[(col1 + 3) * BB + m] * v3;
            } else {           // z
                *(float4*)(g_Z + m * HD + col1) = make_float4(v0, v1, v2, v3);
            }
        }
        grid_barrier();

        // ---------------- phase 2: h + combine ----------------
        unsigned long long acc = 0ull;
#pragma unroll 1
        for (int kc = 0; kc < HD; kc += 64) {
            __syncthreads();
            for (int i = tid; i < 1024; i += GRU_THREADS)
                ((float4*)Hs)[i] = ((const float4*)(g_Hr + kc * 64))[i];
            __syncthreads();
#pragma unroll 8
            for (int kk = 0; kk < 64; ++kk) {
                float h = Hs[kk * 64 + m];
                unsigned long long hh = pack2(h, h);
                unsigned long long w = *(const unsigned long long*)(Whc + (size_t)(kc + kk) * HD + c2);
                acc = ffma2(hh, w, acc);
            }
        }
        {
            float2 a = unpack2(acc);
            const float2 xp = *(const float2*)(g_xproj + ((size_t)s * BB + m) * (3 * HD) +
                                               2 * HD + c2);
            float h0 = tanhf(a.x + xp.x);
            float h1 = tanhf(a.y + xp.y);
            float2 z2 = *(const float2*)(g_Z + m * HD + c2);
            float H0 = Hcur[(c2 + 0) * BB + m];
            float H1 = Hcur[(c2 + 1) * BB + m];
            Hnext[(c2 + 0) * BB + m] = z2.x * H0 + (1.0f - z2.x) * h0;
            Hnext[(c2 + 1) * BB + m] = z2.y * H1 + (1.0f - z2.y) * h1;
        }
        grid_barrier();
        p ^= 1;
    }
    // after 512 steps (even), final H lives in g_H[0]
}

// =====================================================================
// Kernel 3: logits + softmax. grid=64 (one block per batch row).
// =====================================================================
__global__ __launch_bounds__(128) void out_kernel(const float* __restrict__ Whq,
                                                  const float* __restrict__ bq,
                                                  float* __restrict__ out) {
    const int b = blockIdx.x;
    const int t = threadIdx.x;  // 128 threads
    float acc[NO];
#pragma unroll
    for (int o = 0; o < NO; o++) acc[o] = 0.f;
    for (int k = t; k < HD; k += 128) {
        float hv = g_H[0][k * BB + b];
        const float* w = Whq + (size_t)k * NO;
#pragma unroll
        for (int o = 0; o < NO; o++) acc[o] += hv * w[o];
    }
    __shared__ float part[128 * NO];
#pragma unroll
    for (int o = 0; o < NO; o++) part[t * NO + o] = acc[o];
    __syncthreads();
    __shared__ float logits[NO];
    if (t < NO) {
        float sum = bq[t];
        for (int i = 0; i < 128; i++) sum += part[i * NO + t];
        logits[t] = sum;
    }
    __syncthreads();
    if (t == 0) {
        float mx = logits[0];
#pragma unroll
        for (int o = 1; o < NO; o++) mx = fmaxf(mx, logits[o]);
        float e[NO];
        float sum = 0.f;
#pragma unroll
        for (int o = 0; o < NO; o++) { e[o] = __expf(logits[o] - mx); sum += e[o]; }
        float inv = 1.0f / sum;
#pragma unroll
        for (int o = 0; o < NO; o++) out[b * NO + o] = e[o] * inv;
    }
}

// =====================================================================
extern "C" void kernel_launch(void* const* d_in, const int* in_sizes, int n_in,
                              void* d_out, int out_size) {
    const int*   inputs = (const int*)d_in[0];
    const float* emb    = (const float*)d_in[1];
    const float* Wxr = (const float*)d_in[2];
    const float* Whr = (const float*)d_in[3];
    const float* br  = (const float*)d_in[4];
    const float* Wxz = (const float*)d_in[5];
    const float* Whz = (const float*)d_in[6];
    const float* bz  = (const float*)d_in[7];
    const float* Wxc = (const float*)d_in[8];
    const float* Whc = (const float*)d_in[9];
    const float* bc  = (const float*)d_in[10];
    const float* Whq = (const float*)d_in[11];
    const float* bq  = (const float*)d_in[12];
    float* out = (float*)d_out;

    dim3 pg(48, 512);
    proj_kernel<<<pg, 256>>>(inputs, emb, Wxr, Wxz, Wxc, br, bz, bc);
    gru_kernel<<<GRU_BLOCKS, GRU_THREADS>>>(Whr, Whz, Whc);
    out_kernel<<<64, 128>>>(Whq, bq, out);
}

// round 3
// speedup vs baseline: 2.6128x; 2.6023x over previous
#include <cuda_runtime.h>

#define BB 64
#define SS 512
#define EE 512
#define HD 1024
#define NO 10
#define NBLK 128
#define NTHR 256

typedef unsigned long long ull;

// -------- scratch (static device globals) --------
__device__ float g_xproj[(size_t)SS * BB * 3 * HD]; // [s][b][3072]
__device__ float g_H[2][HD * BB];                   // k-major [k][b]
__device__ float g_Hr[HD * BB];                     // k-major
__device__ float g_Z[HD * BB];                      // k-major (col-major like H)
__device__ unsigned g_count;
__device__ unsigned g_gen;

// -------- packed f32x2 helpers --------
__device__ __forceinline__ ull ffma2(ull a, ull b, ull c) {
    ull d; asm("fma.rn.f32x2 %0, %1, %2, %3;" : "=l"(d) : "l"(a), "l"(b), "l"(c));
    return d;
}
__device__ __forceinline__ ull splat2(float x) {
    ull r; asm("mov.b64 %0, {%1,%1};" : "=l"(r) : "f"(x)); return r;
}
__device__ __forceinline__ ull pack2(float lo, float hi) {
    ull r; asm("mov.b64 %0, {%1,%2};" : "=l"(r) : "f"(lo), "f"(hi)); return r;
}
__device__ __forceinline__ float2 unpack2(ull v) {
    float2 f; asm("mov.b64 {%0,%1}, %2;" : "=f"(f.x), "=f"(f.y) : "l"(v)); return f;
}
// 16B L1-bypassing load as two f32x2 pairs
__device__ __forceinline__ void ldcg_2x64(const float* p, ull& a, ull& b) {
    asm("ld.global.cg.v2.u64 {%0,%1}, [%2];" : "=l"(a), "=l"(b) : "l"(p));
}
__device__ __forceinline__ float2 ldcg_f2(const float* p) {
    float2 v; asm("ld.global.cg.v2.f32 {%0,%1}, [%2];" : "=f"(v.x), "=f"(v.y) : "l"(p));
    return v;
}
__device__ __forceinline__ float sigmoid_f(float x) {
    return 1.0f / (1.0f + __expf(-x));
}
__device__ __forceinline__ float tanh_f(float x) {
    float ax = fabsf(x);
    float t = __expf(-2.0f * ax);
    float r = __fdividef(1.0f - t, 1.0f + t);
    return copysignf(r, x);
}

// -------- grid barrier: atomic arrive + monotonic release flag --------
__device__ __forceinline__ void grid_barrier(unsigned target) {
    __syncthreads();
    if (threadIdx.x == 0) {
        __threadfence();
        if (atomicAdd(&g_count, 1u) == NBLK - 1) {
            *(volatile unsigned*)&g_count = 0u;
            __threadfence();
            *(volatile unsigned*)&g_gen = target;
        } else {
            while (*(volatile unsigned*)&g_gen < target) __nanosleep(16);
        }
        __threadfence();
    }
    __syncthreads();
}

__global__ void reset_kernel() { g_count = 0u; g_gen = 0u; }

// =====================================================================
// Kernel 1: input projection with register prefetch + streaming stores
// grid = (48, 512), 256 threads. BM=64, BN=64, BK=16.
// =====================================================================
__global__ __launch_bounds__(256) void proj_kernel(
    const int* __restrict__ inputs, const float* __restrict__ emb,
    const float* __restrict__ Wxr, const float* __restrict__ Wxz,
    const float* __restrict__ Wxc, const float* __restrict__ br,
    const float* __restrict__ bz, const float* __restrict__ bc) {
    const int s  = blockIdx.y;
    const int nt = blockIdx.x;
    const int gate = nt >> 4;
    const float* Wx   = (gate == 0) ? Wxr : ((gate == 1) ? Wxz : Wxc);
    const float* bias = (gate == 0) ? br  : ((gate == 1) ? bz  : bc);
    const int col0 = (nt & 15) * 64;

    __shared__ int tok[64];
    __shared__ __align__(16) float As[16][68];
    __shared__ __align__(16) float Bs[16][64];

    const int tid = threadIdx.x;
    if (tid < 64) tok[tid] = inputs[tid * SS + s];
    __syncthreads();

    const int tx = tid & 15, ty = tid >> 4;
    const int n0 = tx * 4, m0 = ty * 4;
    ull acc[4][2];
#pragma unroll
    for (int i = 0; i < 4; i++) { acc[i][0] = 0ull; acc[i][1] = 0ull; }

    const int lm = tid >> 2, lkq = tid & 3;
    const int bk = tid >> 4, bnq = tid & 15;

    const float* eptr = emb + (size_t)tok[lm] * EE + lkq * 4;
    float4 av = *(const float4*)(eptr);
    float4 bv = *(const float4*)(Wx + (size_t)bk * HD + col0 + bnq * 4);

#pragma unroll 1
    for (int k0 = 0; k0 < EE; k0 += 16) {
        __syncthreads();
        As[lkq * 4 + 0][lm] = av.x;
        As[lkq * 4 + 1][lm] = av.y;
        As[lkq * 4 + 2][lm] = av.z;
        As[lkq * 4 + 3][lm] = av.w;
        *(float4*)&Bs[bk][bnq * 4] = bv;
        __syncthreads();
        // prefetch next tile BEFORE compute (wraps harmlessly on last iter)
        const int kn = (k0 + 16) & (EE - 1);
        float4 av_n = *(const float4*)(eptr + kn);
        float4 bv_n = *(const float4*)(Wx + (size_t)(kn + bk) * HD + col0 + bnq * 4);
#pragma unroll
        for (int kk = 0; kk < 16; ++kk) {
            float4 a4 = *(const float4*)&As[kk][m0];
            ulonglong2 b2 = *(const ulonglong2*)&Bs[kk][n0];
            ull aa;
            aa = splat2(a4.x);
            acc[0][0] = ffma2(aa, b2.x, acc[0][0]);
            acc[0][1] = ffma2(aa, b2.y, acc[0][1]);
            aa = splat2(a4.y);
            acc[1][0] = ffma2(aa, b2.x, acc[1][0]);
            acc[1][1] = ffma2(aa, b2.y, acc[1][1]);
            aa = splat2(a4.z);
            acc[2][0] = ffma2(aa, b2.x, acc[2][0]);
            acc[2][1] = ffma2(aa, b2.y, acc[2][1]);
            aa = splat2(a4.w);
            acc[3][0] = ffma2(aa, b2.x, acc[3][0]);
            acc[3][1] = ffma2(aa, b2.y, acc[3][1]);
        }
        av = av_n; bv = bv_n;
    }
    float4 bi = *(const float4*)(bias + col0 + n0);
#pragma unroll
    for (int i = 0; i < 4; i++) {
        float2 lo = unpack2(acc[i][0]), hi = unpack2(acc[i][1]);
        float4 v = make_float4(lo.x + bi.x, lo.y + bi.y, hi.x + bi.z, hi.y + bi.w);
        __stcs((float4*)(g_xproj + ((size_t)s * BB + m0 + i) * (3 * HD) + gate * HD + col0 + n0), v);
    }
}

// =====================================================================
// Kernel 2: persistent GRU. 128 blocks x 256 threads (8 warps).
// Warp-level k-split (128 k each), register tile 8m x 4c per thread.
// Weights via __ldg (L1-resident, 96KB/block); H/Hr/Z via ld.cg (coherent).
// =====================================================================
__global__ __launch_bounds__(NTHR, 1) void gru_kernel(
    const float* __restrict__ Whr, const float* __restrict__ Whz,
    const float* __restrict__ Whc) {
    __shared__ ull red[8][512];       // 32 KB partial sums
    __shared__ float xp1[64][16];     // 4 KB staged xproj (phase 1)
    __shared__ float xp2[64][8];      // 2 KB staged xproj (phase 2)

    const int tid = threadIdx.x, bx = blockIdx.x;
    const int w = tid >> 5, lane = tid & 31;
    const int mg = lane & 7;          // 8 m per group
    const int cg = lane >> 3;         // 4 col-groups

    // zero-init H0 every launch (graph replays)
    {
        int idx = bx * NTHR + tid;
        if (idx < HD * BB / 4)
            ((float4*)g_H[0])[idx] = make_float4(0.f, 0.f, 0.f, 0.f);
    }
    unsigned bar = 1;
    grid_barrier(bar++);

    const int gate1 = bx >> 6;                 // 0=r, 1=z
    const int colb1 = (bx & 63) * 16;          // gate-local col base (phase 1)
    const float* W1 = gate1 ? Whz : Whr;
    const int colb2 = bx * 8;                  // col base (phase 2)

    int p = 0;
#pragma unroll 1
    for (int s = 0; s < SS; ++s) {
        const float* Hc = g_H[p];
        float* Hn = g_H[p ^ 1];
        const float* xpg = g_xproj + (size_t)s * BB * 3 * HD;

        // issue xproj stage loads early; STS deferred past the k-loops
        float4 xv1, xv2;
        {
            int b = tid >> 2, q = tid & 3;
            xv1 = __ldcs((const float4*)(xpg + b * 3 * HD + gate1 * HD + colb1 + q * 4));
        }
        if (tid < 128) {
            int b = tid >> 1, q = tid & 1;
            xv2 = __ldcs((const float4*)(xpg + b * 3 * HD + 2 * HD + colb2 + q * 4));
        }

        // ---------------- phase 1: r or z (16 cols) ----------------
        ull acc[4][4];
#pragma unroll
        for (int i = 0; i < 4; i++)
#pragma unroll
            for (int j = 0; j < 4; j++) acc[i][j] = 0ull;

        {
            const float* hptr = Hc + (w * 128) * BB + mg * 8;
            const float* wptr = W1 + (size_t)(w * 128) * HD + colb1 + cg * 4;
#pragma unroll 1
            for (int k = 0; k < 128; k += 4) {
#pragma unroll
                for (int u = 0; u < 4; ++u) {
                    ull h0, h1, h2, h3;
                    ldcg_2x64(hptr, h0, h1);
                    ldcg_2x64(hptr + 4, h2, h3);
                    float4 wv = __ldg((const float4*)wptr);
                    ull w0 = splat2(wv.x), w1 = splat2(wv.y);
                    ull w2 = splat2(wv.z), w3 = splat2(wv.w);
                    acc[0][0] = ffma2(h0, w0, acc[0][0]);
                    acc[0][1] = ffma2(h0, w1, acc[0][1]);
                    acc[0][2] = ffma2(h0, w2, acc[0][2]);
                    acc[0][3] = ffma2(h0, w3, acc[0][3]);
                    acc[1][0] = ffma2(h1, w0, acc[1][0]);
                    acc[1][1] = ffma2(h1, w1, acc[1][1]);
                    acc[1][2] = ffma2(h1, w2, acc[1][2]);
                    acc[1][3] = ffma2(h1, w3, acc[1][3]);
                    acc[2][0] = ffma2(h2, w0, acc[2][0]);
                    acc[2][1] = ffma2(h2, w1, acc[2][1]);
                    acc[2][2] = ffma2(h2, w2, acc[2][2]);
                    acc[2][3] = ffma2(h2, w3, acc[2][3]);
                    acc[3][0] = ffma2(h3, w0, acc[3][0]);
                    acc[3][1] = ffma2(h3, w1, acc[3][1]);
                    acc[3][2] = ffma2(h3, w2, acc[3][2]);
                    acc[3][3] = ffma2(h3, w3, acc[3][3]);
                    hptr += BB; wptr += HD;
                }
            }
        }
        // store partials + stage xproj
#pragma unroll
        for (int i = 0; i < 4; i++)
#pragma unroll
            for (int j = 0; j < 4; j++)
                red[w][(mg * 4 + i) * 16 + cg * 4 + j] = acc[i][j];
        {
            int b = tid >> 2, q = tid & 3;
            *(float4*)&xp1[b][q * 4] = xv1;
        }
        if (tid < 128) {
            int b = tid >> 1, q = tid & 1;
            *(float4*)&xp2[b][q * 4] = xv2;
        }
        __syncthreads();

        // reduce 8 partials + epilogue (2 outputs/thread)
#pragma unroll
        for (int rep = 0; rep < 2; ++rep) {
            int o = tid + rep * 256;
            float2 sum = make_float2(0.f, 0.f);
#pragma unroll
            for (int ww = 0; ww < 8; ++ww) {
                float2 v = unpack2(red[ww][o]);
                sum.x += v.x; sum.y += v.y;
            }
            int mp = o >> 4, c = o & 15;
            int colg = colb1 + c;
            float v0 = sigmoid_f(sum.x + xp1[2 * mp][c]);
            float v1 = sigmoid_f(sum.y + xp1[2 * mp + 1][c]);
            if (gate1 == 0) {
                float2 hp = ldcg_f2(Hc + colg * BB + 2 * mp);
                float2 hr = make_float2(hp.x * v0, hp.y * v1);
                *(float2*)(g_Hr + colg * BB + 2 * mp) = hr;
            } else {
                *(float2*)(g_Z + colg * BB + 2 * mp) = make_float2(v0, v1);
            }
        }
        grid_barrier(bar++);

        // ---------------- phase 2: candidate h (8 cols) ----------------
        ull acc2[4][2];
#pragma unroll
        for (int i = 0; i < 4; i++) { acc2[i][0] = 0ull; acc2[i][1] = 0ull; }
        {
            const float* hptr = g_Hr + (w * 128) * BB + mg * 8;
            const float* wptr = Whc + (size_t)(w * 128) * HD + colb2 + cg * 2;
#pragma unroll 1
            for (int k = 0; k < 128; k += 4) {
#pragma unroll
                for (int u = 0; u < 4; ++u) {
                    ull h0, h1, h2, h3;
                    ldcg_2x64(hptr, h0, h1);
                    ldcg_2x64(hptr + 4, h2, h3);
                    float2 wv = __ldg((const float2*)wptr);
                    ull w0 = splat2(wv.x), w1 = splat2(wv.y);
                    acc2[0][0] = ffma2(h0, w0, acc2[0][0]);
                    acc2[0][1] = ffma2(h0, w1, acc2[0][1]);
                    acc2[1][0] = ffma2(h1, w0, acc2[1][0]);
                    acc2[1][1] = ffma2(h1, w1, acc2[1][1]);
                    acc2[2][0] = ffma2(h2, w0, acc2[2][0]);
                    acc2[2][1] = ffma2(h2, w1, acc2[2][1]);
                    acc2[3][0] = ffma2(h3, w0, acc2[3][0]);
                    acc2[3][1] = ffma2(h3, w1, acc2[3][1]);
                    hptr += BB; wptr += HD;
                }
            }
        }
#pragma unroll
        for (int i = 0; i < 4; i++)
#pragma unroll
            for (int j = 0; j < 2; j++)
                red[w][(mg * 4 + i) * 8 + cg * 2 + j] = acc2[i][j];
        __syncthreads();

        {
            int o = tid;  // 256 outputs
            float2 sum = make_float2(0.f, 0.f);
#pragma unroll
            for (int ww = 0; ww < 8; ++ww) {
                float2 v = unpack2(red[ww][o]);
                sum.x += v.x; sum.y += v.y;
            }
            int mp = o >> 3, c = o & 7;
            int colg = colb2 + c;
            float h0 = tanh_f(sum.x + xp2[2 * mp][c]);
            float h1 = tanh_f(sum.y + xp2[2 * mp + 1][c]);
            float2 z  = ldcg_f2(g_Z + colg * BB + 2 * mp);
            float2 hp = ldcg_f2(Hc + colg * BB + 2 * mp);
            float2 hn = make_float2(z.x * hp.x + (1.f - z.x) * h0,
                                    z.y * hp.y + (1.f - z.y) * h1);
            *(float2*)(Hn + colg * BB + 2 * mp) = hn;
        }
        grid_barrier(bar++);
        p ^= 1;
    }
}

// =====================================================================
// Kernel 3: logits + softmax
// =====================================================================
__global__ __launch_bounds__(128) void out_kernel(const float* __restrict__ Whq,
                                                  const float* __restrict__ bq,
                                                  float* __restrict__ out) {
    const int b = blockIdx.x;
    const int t = threadIdx.x;
    float acc[NO];
#pragma unroll
    for (int o = 0; o < NO; o++) acc[o] = 0.f;
    for (int k = t; k < HD; k += 128) {
        float hv = g_H[0][k * BB + b];
        const float* wp = Whq + (size_t)k * NO;
#pragma unroll
        for (int o = 0; o < NO; o++) acc[o] += hv * wp[o];
    }
    __shared__ float part[128 * NO];
#pragma unroll
    for (int o = 0; o < NO; o++) part[t * NO + o] = acc[o];
    __syncthreads();
    __shared__ float logits[NO];
    if (t < NO) {
        float sum = bq[t];
        for (int i = 0; i < 128; i++) sum += part[i * NO + t];
        logits[t] = sum;
    }
    __syncthreads();
    if (t == 0) {
        float mx = logits[0];
#pragma unroll
        for (int o = 1; o < NO; o++) mx = fmaxf(mx, logits[o]);
        float e[NO]; float sum = 0.f;
#pragma unroll
        for (int o = 0; o < NO; o++) { e[o] = __expf(logits[o] - mx); sum += e[o]; }
        float inv = 1.0f / sum;
#pragma unroll
        for (int o = 0; o < NO; o++) out[b * NO + o] = e[o] * inv;
    }
}

// =====================================================================
extern "C" void kernel_launch(void* const* d_in, const int* in_sizes, int n_in,
                              void* d_out, int out_size) {
    const int*   inputs = (const int*)d_in[0];
    const float* emb = (const float*)d_in[1];
    const float* Wxr = (const float*)d_in[2];
    const float* Whr = (const float*)d_in[3];
    const float* br  = (const float*)d_in[4];
    const float* Wxz = (const float*)d_in[5];
    const float* Whz = (const float*)d_in[6];
    const float* bz  = (const float*)d_in[7];
    const float* Wxc = (const float*)d_in[8];
    const float* Whc = (const float*)d_in[9];
    const float* bc  = (const float*)d_in[10];
    const float* Whq = (const float*)d_in[11];
    const float* bq  = (const float*)d_in[12];
    float* out = (float*)d_out;

    reset_kernel<<<1, 1>>>();
    dim3 pg(48, 512);
    proj_kernel<<<pg, 256>>>(inputs, emb, Wxr, Wxz, Wxc, br, bz, bc);
    gru_kernel<<<NBLK, NTHR>>>(Whr, Whz, Whc);
    out_kernel<<<64, 128>>>(Whq, bq, out);
}

// round 4
// speedup vs baseline: 2.8058x; 1.0739x over previous
#include <cuda_runtime.h>

#define BB 64
#define SS 512
#define EE 512
#define HD 1024
#define NO 10
#define NBLK 128
#define GTHR 512

typedef unsigned long long ull;

// -------- scratch --------
__device__ float g_xproj[(size_t)SS * BB * 3 * HD]; // [s][b][3072]
__device__ float g_H[2][HD * BB];                   // k-major [k][b]
__device__ float g_Hr[HD * BB];
__device__ float g_Z[HD * BB];
__device__ unsigned g_count;
__device__ unsigned g_gen;

// -------- packed f32x2 helpers --------
__device__ __forceinline__ ull ffma2(ull a, ull b, ull c) {
    ull d; asm("fma.rn.f32x2 %0, %1, %2, %3;" : "=l"(d) : "l"(a), "l"(b), "l"(c));
    return d;
}
__device__ __forceinline__ ull splat2(float x) {
    ull r; asm("mov.b64 %0, {%1,%1};" : "=l"(r) : "f"(x)); return r;
}
__device__ __forceinline__ float2 unpack2(ull v) {
    float2 f; asm("mov.b64 {%0,%1}, %2;" : "=f"(f.x), "=f"(f.y) : "l"(v)); return f;
}
__device__ __forceinline__ void ldcg_2x64(const float* p, ull& a, ull& b) {
    asm("ld.global.cg.v2.u64 {%0,%1}, [%2];" : "=l"(a), "=l"(b) : "l"(p));
}
__device__ __forceinline__ float2 ldcg_f2(const float* p) {
    float2 v; asm("ld.global.cg.v2.f32 {%0,%1}, [%2];" : "=f"(v.x), "=f"(v.y) : "l"(p));
    return v;
}
__device__ __forceinline__ float sigmoid_f(float x) {
    return 1.0f / (1.0f + __expf(-x));
}
__device__ __forceinline__ float tanh_f(float x) {
    float ax = fabsf(x);
    float t = __expf(-2.0f * ax);
    float r = __fdividef(1.0f - t, 1.0f + t);
    return copysignf(r, x);
}

// -------- grid barrier: atomic arrive + release/acquire flag --------
__device__ __forceinline__ void grid_barrier(unsigned target) {
    __syncthreads();
    if (threadIdx.x == 0) {
        __threadfence();
        if (atomicAdd(&g_count, 1u) == NBLK - 1) {
            *(volatile unsigned*)&g_count = 0u;
            asm volatile("st.release.gpu.u32 [%0], %1;" :: "l"(&g_gen), "r"(target) : "memory");
        } else {
            unsigned v;
            do {
                asm volatile("ld.acquire.gpu.u32 %0, [%1];" : "=r"(v) : "l"(&g_gen) : "memory");
            } while (v < target);
        }
    }
    __syncthreads();
}

__global__ void reset_kernel() { g_count = 0u; g_gen = 0u; }

// =====================================================================
// Kernel 1: input projection, double-buffered smem, 1 sync per tile
// grid = (48, 512), 256 threads. BM=64, BN=64, BK=16.
// =====================================================================
__global__ __launch_bounds__(256) void proj_kernel(
    const int* __restrict__ inputs, const float* __restrict__ emb,
    const float* __restrict__ Wxr, const float* __restrict__ Wxz,
    const float* __restrict__ Wxc, const float* __restrict__ br,
    const float* __restrict__ bz, const float* __restrict__ bc) {
    const int s  = blockIdx.y;
    const int nt = blockIdx.x;
    const int gate = nt >> 4;
    const float* Wx   = (gate == 0) ? Wxr : ((gate == 1) ? Wxz : Wxc);
    const float* bias = (gate == 0) ? br  : ((gate == 1) ? bz  : bc);
    const int col0 = (nt & 15) * 64;

    __shared__ int tok[64];
    __shared__ __align__(16) float As[2][16][68];
    __shared__ __align__(16) float Bs[2][16][64];

    const int tid = threadIdx.x;
    if (tid < 64) tok[tid] = inputs[tid * SS + s];
    __syncthreads();

    const int tx = tid & 15, ty = tid >> 4;
    const int n0 = tx * 4, m0 = ty * 4;
    ull acc[4][2];
#pragma unroll
    for (int i = 0; i < 4; i++) { acc[i][0] = 0ull; acc[i][1] = 0ull; }

    const int lm = tid >> 2, lkq = tid & 3;
    const int bk = tid >> 4, bnq = tid & 15;

    const float* eptr = emb + (size_t)tok[lm] * EE + lkq * 4;
    // stage tile 0
    {
        float4 av = *(const float4*)(eptr);
        float4 bv = *(const float4*)(Wx + (size_t)bk * HD + col0 + bnq * 4);
        As[0][lkq * 4 + 0][lm] = av.x;
        As[0][lkq * 4 + 1][lm] = av.y;
        As[0][lkq * 4 + 2][lm] = av.z;
        As[0][lkq * 4 + 3][lm] = av.w;
        *(float4*)&Bs[0][bk][bnq * 4] = bv;
    }
    __syncthreads();

    int p = 0;
#pragma unroll 1
    for (int k0 = 0; k0 < EE; k0 += 16) {
        float4 av_n, bv_n;
        const bool more = (k0 + 16 < EE);
        if (more) {
            av_n = *(const float4*)(eptr + k0 + 16);
            bv_n = *(const float4*)(Wx + (size_t)(k0 + 16 + bk) * HD + col0 + bnq * 4);
        }
#pragma unroll
        for (int kk = 0; kk < 16; ++kk) {
            float4 a4 = *(const float4*)&As[p][kk][m0];
            ulonglong2 b2 = *(const ulonglong2*)&Bs[p][kk][n0];
            ull aa;
            aa = splat2(a4.x);
            acc[0][0] = ffma2(aa, b2.x, acc[0][0]);
            acc[0][1] = ffma2(aa, b2.y, acc[0][1]);
            aa = splat2(a4.y);
            acc[1][0] = ffma2(aa, b2.x, acc[1][0]);
            acc[1][1] = ffma2(aa, b2.y, acc[1][1]);
            aa = splat2(a4.z);
            acc[2][0] = ffma2(aa, b2.x, acc[2][0]);
            acc[2][1] = ffma2(aa, b2.y, acc[2][1]);
            aa = splat2(a4.w);
            acc[3][0] = ffma2(aa, b2.x, acc[3][0]);
            acc[3][1] = ffma2(aa, b2.y, acc[3][1]);
        }
        if (more) {
            As[p ^ 1][lkq * 4 + 0][lm] = av_n.x;
            As[p ^ 1][lkq * 4 + 1][lm] = av_n.y;
            As[p ^ 1][lkq * 4 + 2][lm] = av_n.z;
            As[p ^ 1][lkq * 4 + 3][lm] = av_n.w;
            *(float4*)&Bs[p ^ 1][bk][bnq * 4] = bv_n;
            __syncthreads();
        }
        p ^= 1;
    }
    float4 bi = *(const float4*)(bias + col0 + n0);
#pragma unroll
    for (int i = 0; i < 4; i++) {
        float2 lo = unpack2(acc[i][0]), hi = unpack2(acc[i][1]);
        float4 v = make_float4(lo.x + bi.x, lo.y + bi.y, hi.x + bi.z, hi.y + bi.w);
        __stcs((float4*)(g_xproj + ((size_t)s * BB + m0 + i) * (3 * HD) + gate * HD + col0 + n0), v);
    }
}

// =====================================================================
// Kernel 2: persistent GRU. 128 blocks x 512 threads (16 warps).
// k-split 16 warps x 64 k. Two-stage smem reduction. Register tile 8m x 4c.
// =====================================================================
__global__ __launch_bounds__(GTHR, 1) void gru_kernel(
    const float* __restrict__ Whr, const float* __restrict__ Whz,
    const float* __restrict__ Whc) {
    __shared__ ull red[8][512];       // 32 KB
    __shared__ float xp1[64][16];     // 4 KB
    __shared__ float xp2[64][8];      // 2 KB

    const int tid = threadIdx.x, bx = blockIdx.x;
    const int w = tid >> 5, lane = tid & 31;
    const int mg = lane & 7;          // m-group (8 rows)
    const int cg = lane >> 3;         // col-group (4)

    // zero-init H0 every launch
    {
        int idx = bx * GTHR + tid;
        if (idx < HD * BB / 4)
            ((float4*)g_H[0])[idx] = make_float4(0.f, 0.f, 0.f, 0.f);
    }
    unsigned bar = 1;
    grid_barrier(bar++);

    const int gate1 = bx >> 6;
    const int colb1 = (bx & 63) * 16;
    const float* W1 = gate1 ? Whz : Whr;
    const int colb2 = bx * 8;

    int p = 0;
#pragma unroll 1
    for (int s = 0; s < SS; ++s) {
        const float* Hc = g_H[p];
        float* Hn = g_H[p ^ 1];
        const float* xpg = g_xproj + (size_t)s * BB * 3 * HD;

        // stage xproj early (latency hides under k-loop)
        float2 xv1, xv2;
        {
            int b = tid >> 3, q = tid & 7;
            xv1 = __ldcs((const float2*)(xpg + b * 3 * HD + gate1 * HD + colb1 + q * 2));
        }
        if (tid < 256) {
            int b = tid >> 2, q = tid & 3;
            xv2 = __ldcs((const float2*)(xpg + b * 3 * HD + 2 * HD + colb2 + q * 2));
        }

        // ---------------- phase 1: r or z (16 cols, 64 k per warp) --------
        ull acc[4][4];
#pragma unroll
        for (int i = 0; i < 4; i++)
#pragma unroll
            for (int j = 0; j < 4; j++) acc[i][j] = 0ull;
        {
            const float* hptr = Hc + (w * 64) * BB + mg * 8;
            const float* wptr = W1 + (size_t)(w * 64) * HD + colb1 + cg * 4;
#pragma unroll 1
            for (int k = 0; k < 64; k += 8) {
#pragma unroll
                for (int u = 0; u < 8; ++u) {
                    ull h0, h1, h2, h3;
                    ldcg_2x64(hptr, h0, h1);
                    ldcg_2x64(hptr + 4, h2, h3);
                    float4 wv = __ldg((const float4*)wptr);
                    ull w0 = splat2(wv.x), w1 = splat2(wv.y);
                    ull w2 = splat2(wv.z), w3 = splat2(wv.w);
                    acc[0][0] = ffma2(h0, w0, acc[0][0]);
                    acc[0][1] = ffma2(h0, w1, acc[0][1]);
                    acc[0][2] = ffma2(h0, w2, acc[0][2]);
                    acc[0][3] = ffma2(h0, w3, acc[0][3]);
                    acc[1][0] = ffma2(h1, w0, acc[1][0]);
                    acc[1][1] = ffma2(h1, w1, acc[1][1]);
                    acc[1][2] = ffma2(h1, w2, acc[1][2]);
                    acc[1][3] = ffma2(h1, w3, acc[1][3]);
                    acc[2][0] = ffma2(h2, w0, acc[2][0]);
                    acc[2][1] = ffma2(h2, w1, acc[2][1]);
                    acc[2][2] = ffma2(h2, w2, acc[2][2]);
                    acc[2][3] = ffma2(h2, w3, acc[2][3]);
                    acc[3][0] = ffma2(h3, w0, acc[3][0]);
                    acc[3][1] = ffma2(h3, w1, acc[3][1]);
                    acc[3][2] = ffma2(h3, w2, acc[3][2]);
                    acc[3][3] = ffma2(h3, w3, acc[3][3]);
                    hptr += BB; wptr += HD;
                }
            }
        }
        // two-stage reduction into 8 banks
        if (w < 8) {
#pragma unroll
            for (int i = 0; i < 4; i++)
#pragma unroll
                for (int j = 0; j < 4; j++)
                    red[w][(mg * 4 + i) * 16 + cg * 4 + j] = acc[i][j];
        }
        // stage xproj into smem
        {
            int b = tid >> 3, q = tid & 7;
            *(float2*)&xp1[b][q * 2] = xv1;
        }
        if (tid < 256) {
            int b = tid >> 2, q = tid & 3;
            *(float2*)&xp2[b][q * 2] = xv2;
        }
        __syncthreads();
        if (w >= 8) {
#pragma unroll
            for (int i = 0; i < 4; i++)
#pragma unroll
                for (int j = 0; j < 4; j++) {
                    int slot = (mg * 4 + i) * 16 + cg * 4 + j;
                    float2 a = unpack2(acc[i][j]);
                    float2 c = unpack2(red[w - 8][slot]);
                    a.x += c.x; a.y += c.y;
                    red[w - 8][slot] = *(ull*)&a;
                }
        }
        __syncthreads();

        // epilogue: 512 outputs (one f32x2 slot per thread)
        {
            int o = tid;
            float2 sum = make_float2(0.f, 0.f);
#pragma unroll
            for (int ww = 0; ww < 8; ++ww) {
                float2 v = unpack2(red[ww][o]);
                sum.x += v.x; sum.y += v.y;
            }
            int mp = o >> 4, c = o & 15;
            int colg = colb1 + c;
            float v0 = sigmoid_f(sum.x + xp1[2 * mp][c]);
            float v1 = sigmoid_f(sum.y + xp1[2 * mp + 1][c]);
            if (gate1 == 0) {
                float2 hp = ldcg_f2(Hc + colg * BB + 2 * mp);
                *(float2*)(g_Hr + colg * BB + 2 * mp) = make_float2(hp.x * v0, hp.y * v1);
            } else {
                *(float2*)(g_Z + colg * BB + 2 * mp) = make_float2(v0, v1);
            }
        }
        grid_barrier(bar++);

        // ---------------- phase 2: candidate h (8 cols) ----------------
        ull acc2[4][2];
#pragma unroll
        for (int i = 0; i < 4; i++) { acc2[i][0] = 0ull; acc2[i][1] = 0ull; }
        {
            const float* hptr = g_Hr + (w * 64) * BB + mg * 8;
            const float* wptr = Whc + (size_t)(w * 64) * HD + colb2 + cg * 2;
#pragma unroll 1
            for (int k = 0; k < 64; k += 8) {
#pragma unroll
                for (int u = 0; u < 8; ++u) {
                    ull h0, h1, h2, h3;
                    ldcg_2x64(hptr, h0, h1);
                    ldcg_2x64(hptr + 4, h2, h3);
                    float2 wv = __ldg((const float2*)wptr);
                    ull w0 = splat2(wv.x), w1 = splat2(wv.y);
                    acc2[0][0] = ffma2(h0, w0, acc2[0][0]);
                    acc2[0][1] = ffma2(h0, w1, acc2[0][1]);
                    acc2[1][0] = ffma2(h1, w0, acc2[1][0]);
                    acc2[1][1] = ffma2(h1, w1, acc2[1][1]);
                    acc2[2][0] = ffma2(h2, w0, acc2[2][0]);
                    acc2[2][1] = ffma2(h2, w1, acc2[2][1]);
                    acc2[3][0] = ffma2(h3, w0, acc2[3][0]);
                    acc2[3][1] = ffma2(h3, w1, acc2[3][1]);
                    hptr += BB; wptr += HD;
                }
            }
        }
        if (w < 8) {
#pragma unroll
            for (int i = 0; i < 4; i++)
#pragma unroll
                for (int j = 0; j < 2; j++)
                    red[w][(mg * 4 + i) * 8 + cg * 2 + j] = acc2[i][j];
        }
        __syncthreads();
        if (w >= 8) {
#pragma unroll
            for (int i = 0; i < 4; i++)
#pragma unroll
                for (int j = 0; j < 2; j++) {
                    int slot = (mg * 4 + i) * 8 + cg * 2 + j;
                    float2 a = unpack2(acc2[i][j]);
                    float2 c = unpack2(red[w - 8][slot]);
                    a.x += c.x; a.y += c.y;
                    red[w - 8][slot] = *(ull*)&a;
                }
        }
        __syncthreads();

        if (tid < 256) {
            int o = tid;
            float2 sum = make_float2(0.f, 0.f);
#pragma unroll
            for (int ww = 0; ww < 8; ++ww) {
                float2 v = unpack2(red[ww][o]);
                sum.x += v.x; sum.y += v.y;
            }
            int mp = o >> 3, c = o & 7;
            int colg = colb2 + c;
            float h0 = tanh_f(sum.x + xp2[2 * mp][c]);
            float h1 = tanh_f(sum.y + xp2[2 * mp + 1][c]);
            float2 z  = ldcg_f2(g_Z + colg * BB + 2 * mp);
            float2 hp = ldcg_f2(Hc + colg * BB + 2 * mp);
            *(float2*)(Hn + colg * BB + 2 * mp) =
                make_float2(z.x * hp.x + (1.f - z.x) * h0,
                            z.y * hp.y + (1.f - z.y) * h1);
        }
        grid_barrier(bar++);
        p ^= 1;
    }
}

// =====================================================================
// Kernel 3: logits + softmax
// =====================================================================
__global__ __launch_bounds__(128) void out_kernel(const float* __restrict__ Whq,
                                                  const float* __restrict__ bq,
                                                  float* __restrict__ out) {
    const int b = blockIdx.x;
    const int t = threadIdx.x;
    float acc[NO];
#pragma unroll
    for (int o = 0; o < NO; o++) acc[o] = 0.f;
    for (int k = t; k < HD; k += 128) {
        float hv = g_H[0][k * BB + b];
        const float* wp = Whq + (size_t)k * NO;
#pragma unroll
        for (int o = 0; o < NO; o++) acc[o] += hv * wp[o];
    }
    __shared__ float part[128 * NO];
#pragma unroll
    for (int o = 0; o < NO; o++) part[t * NO + o] = acc[o];
    __syncthreads();
    __shared__ float logits[NO];
    if (t < NO) {
        float sum = bq[t];
        for (int i = 0; i < 128; i++) sum += part[i * NO + t];
        logits[t] = sum;
    }
    __syncthreads();
    if (t == 0) {
        float mx = logits[0];
#pragma unroll
        for (int o = 1; o < NO; o++) mx = fmaxf(mx, logits[o]);
        float e[NO]; float sum = 0.f;
#pragma unroll
        for (int o = 0; o < NO; o++) { e[o] = __expf(logits[o] - mx); sum += e[o]; }
        float inv = 1.0f / sum;
#pragma unroll
        for (int o = 0; o < NO; o++) out[b * NO + o] = e[o] * inv;
    }
}

// =====================================================================
extern "C" void kernel_launch(void* const* d_in, const int* in_sizes, int n_in,
                              void* d_out, int out_size) {
    const int*   inputs = (const int*)d_in[0];
    const float* emb = (const float*)d_in[1];
    const float* Wxr = (const float*)d_in[2];
    const float* Whr = (const float*)d_in[3];
    const float* br  = (const float*)d_in[4];
    const float* Wxz = (const float*)d_in[5];
    const float* Whz = (const float*)d_in[6];
    const float* bz  = (const float*)d_in[7];
    const float* Wxc = (const float*)d_in[8];
    const float* Whc = (const float*)d_in[9];
    const float* bc  = (const float*)d_in[10];
    const float* Whq = (const float*)d_in[11];
    const float* bq  = (const float*)d_in[12];
    float* out = (float*)d_out;

    reset_kernel<<<1, 1>>>();
    dim3 pg(48, 512);
    proj_kernel<<<pg, 256>>>(inputs, emb, Wxr, Wxz, Wxc, br, bz, bc);
    gru_kernel<<<NBLK, GTHR>>>(Whr, Whz, Whc);
    out_kernel<<<64, 128>>>(Whq, bq, out);
}

// round 5
// speedup vs baseline: 3.0705x; 1.0943x over previous
#include <cuda_runtime.h>

#define BB 64
#define SS 512
#define EE 512
#define HD 1024
#define NO 10
#define NBLK 128
#define GTHR 512

typedef unsigned long long ull;

// -------- scratch --------
__device__ float g_xproj[(size_t)SS * BB * 3 * HD]; // [s][b][3072]
__device__ float g_H[2][HD * BB];                   // k-major [k][b]
__device__ float g_Hr[HD * BB];
__device__ float g_Z[HD * BB];
__device__ unsigned g_arrive[NBLK * 32];            // 128B-strided arrive flags
__device__ unsigned g_gen;

// -------- packed f32x2 helpers --------
__device__ __forceinline__ ull ffma2(ull a, ull b, ull c) {
    ull d; asm("fma.rn.f32x2 %0, %1, %2, %3;" : "=l"(d) : "l"(a), "l"(b), "l"(c));
    return d;
}
__device__ __forceinline__ ull splat2(float x) {
    ull r; asm("mov.b64 %0, {%1,%1};" : "=l"(r) : "f"(x)); return r;
}
__device__ __forceinline__ float2 unpack2(ull v) {
    float2 f; asm("mov.b64 {%0,%1}, %2;" : "=f"(f.x), "=f"(f.y) : "l"(v)); return f;
}
__device__ __forceinline__ void ldcg_2x64(const float* p, ull& a, ull& b) {
    asm("ld.global.cg.v2.u64 {%0,%1}, [%2];" : "=l"(a), "=l"(b) : "l"(p));
}
__device__ __forceinline__ float2 ldcg_f2(const float* p) {
    float2 v; asm("ld.global.cg.v2.f32 {%0,%1}, [%2];" : "=f"(v.x), "=f"(v.y) : "l"(p));
    return v;
}
__device__ __forceinline__ float sigmoid_f(float x) {
    return 1.0f / (1.0f + __expf(-x));
}
__device__ __forceinline__ float tanh_f(float x) {
    float ax = fabsf(x);
    float t = __expf(-2.0f * ax);
    float r = __fdividef(1.0f - t, 1.0f + t);
    return copysignf(r, x);
}

// -------- grid barrier v3: flag-array arrive + aggregator + release ------
__device__ __forceinline__ void grid_barrier(unsigned target, int bx) {
    __syncthreads();
    if (threadIdx.x == 0) {
        __threadfence();
        asm volatile("st.release.gpu.u32 [%0], %1;"
                     :: "l"(&g_arrive[bx * 32]), "r"(target) : "memory");
    }
    if (bx == 0) {
        if (threadIdx.x < NBLK) {
            const unsigned* p = &g_arrive[threadIdx.x * 32];
            unsigned v;
            do {
                asm volatile("ld.acquire.gpu.u32 %0, [%1];" : "=r"(v) : "l"(p) : "memory");
            } while (v < target);
        }
        __syncthreads();
        if (threadIdx.x == 0)
            asm volatile("st.release.gpu.u32 [%0], %1;"
                         :: "l"(&g_gen), "r"(target) : "memory");
    } else if (threadIdx.x == 0) {
        unsigned v;
        do {
            asm volatile("ld.acquire.gpu.u32 %0, [%1];" : "=r"(v) : "l"(&g_gen) : "memory");
        } while (v < target);
    }
    __syncthreads();
}

__global__ void reset_kernel() {
    int t = threadIdx.x;
    for (int i = t; i < NBLK * 32; i += blockDim.x) g_arrive[i] = 0u;
    if (t == 0) g_gen = 0u;
}

// =====================================================================
// Kernel 1: input projection, double-buffered smem
// =====================================================================
__global__ __launch_bounds__(256) void proj_kernel(
    const int* __restrict__ inputs, const float* __restrict__ emb,
    const float* __restrict__ Wxr, const float* __restrict__ Wxz,
    const float* __restrict__ Wxc, const float* __restrict__ br,
    const float* __restrict__ bz, const float* __restrict__ bc) {
    const int s  = blockIdx.y;
    const int nt = blockIdx.x;
    const int gate = nt >> 4;
    const float* Wx   = (gate == 0) ? Wxr : ((gate == 1) ? Wxz : Wxc);
    const float* bias = (gate == 0) ? br  : ((gate == 1) ? bz  : bc);
    const int col0 = (nt & 15) * 64;

    __shared__ int tok[64];
    __shared__ __align__(16) float As[2][16][68];
    __shared__ __align__(16) float Bs[2][16][64];

    const int tid = threadIdx.x;
    if (tid < 64) tok[tid] = inputs[tid * SS + s];
    __syncthreads();

    const int tx = tid & 15, ty = tid >> 4;
    const int n0 = tx * 4, m0 = ty * 4;
    ull acc[4][2];
#pragma unroll
    for (int i = 0; i < 4; i++) { acc[i][0] = 0ull; acc[i][1] = 0ull; }

    const int lm = tid >> 2, lkq = tid & 3;
    const int bk = tid >> 4, bnq = tid & 15;

    const float* eptr = emb + (size_t)tok[lm] * EE + lkq * 4;
    {
        float4 av = *(const float4*)(eptr);
        float4 bv = *(const float4*)(Wx + (size_t)bk * HD + col0 + bnq * 4);
        As[0][lkq * 4 + 0][lm] = av.x;
        As[0][lkq * 4 + 1][lm] = av.y;
        As[0][lkq * 4 + 2][lm] = av.z;
        As[0][lkq * 4 + 3][lm] = av.w;
        *(float4*)&Bs[0][bk][bnq * 4] = bv;
    }
    __syncthreads();

    int p = 0;
#pragma unroll 1
    for (int k0 = 0; k0 < EE; k0 += 16) {
        float4 av_n, bv_n;
        const bool more = (k0 + 16 < EE);
        if (more) {
            av_n = *(const float4*)(eptr + k0 + 16);
            bv_n = *(const float4*)(Wx + (size_t)(k0 + 16 + bk) * HD + col0 + bnq * 4);
        }
#pragma unroll
        for (int kk = 0; kk < 16; ++kk) {
            float4 a4 = *(const float4*)&As[p][kk][m0];
            ulonglong2 b2 = *(const ulonglong2*)&Bs[p][kk][n0];
            ull aa;
            aa = splat2(a4.x);
            acc[0][0] = ffma2(aa, b2.x, acc[0][0]);
            acc[0][1] = ffma2(aa, b2.y, acc[0][1]);
            aa = splat2(a4.y);
            acc[1][0] = ffma2(aa, b2.x, acc[1][0]);
            acc[1][1] = ffma2(aa, b2.y, acc[1][1]);
            aa = splat2(a4.z);
            acc[2][0] = ffma2(aa, b2.x, acc[2][0]);
            acc[2][1] = ffma2(aa, b2.y, acc[2][1]);
            aa = splat2(a4.w);
            acc[3][0] = ffma2(aa, b2.x, acc[3][0]);
            acc[3][1] = ffma2(aa, b2.y, acc[3][1]);
        }
        if (more) {
            As[p ^ 1][lkq * 4 + 0][lm] = av_n.x;
            As[p ^ 1][lkq * 4 + 1][lm] = av_n.y;
            As[p ^ 1][lkq * 4 + 2][lm] = av_n.z;
            As[p ^ 1][lkq * 4 + 3][lm] = av_n.w;
            *(float4*)&Bs[p ^ 1][bk][bnq * 4] = bv_n;
            __syncthreads();
        }
        p ^= 1;
    }
    float4 bi = *(const float4*)(bias + col0 + n0);
#pragma unroll
    for (int i = 0; i < 4; i++) {
        float2 lo = unpack2(acc[i][0]), hi = unpack2(acc[i][1]);
        float4 v = make_float4(lo.x + bi.x, lo.y + bi.y, hi.x + bi.z, hi.y + bi.w);
        __stcs((float4*)(g_xproj + ((size_t)s * BB + m0 + i) * (3 * HD) + gate * HD + col0 + n0), v);
    }
}

// =====================================================================
// Kernel 2: persistent GRU. 128 blocks x 512 threads (16 warps).
// Conflict-free lane-linear reduction layout.
// =====================================================================
__global__ __launch_bounds__(GTHR, 1) void gru_kernel(
    const float* __restrict__ Whr, const float* __restrict__ Whz,
    const float* __restrict__ Whc) {
    __shared__ ull red[8][512];        // 32 KB, lane-linear slots
    __shared__ float xp1[64 * 18];     // 4.5 KB (row stride 18 -> 8B aligned)
    __shared__ float xp2[64 * 10];     // 2.5 KB

    const int tid = threadIdx.x, bx = blockIdx.x;
    const int w = tid >> 5, lane = tid & 31;
    const int mg = lane & 7;
    const int cg = lane >> 3;

    // zero-init H0 every launch
    {
        int idx = bx * GTHR + tid;
        if (idx < HD * BB / 4)
            ((float4*)g_H[0])[idx] = make_float4(0.f, 0.f, 0.f, 0.f);
    }
    unsigned bar = 1;
    grid_barrier(bar++, bx);

    const int gate1 = bx >> 6;
    const int colb1 = (bx & 63) * 16;
    const float* W1 = gate1 ? Whz : Whr;
    const int colb2 = bx * 8;

    int p = 0;
#pragma unroll 1
    for (int s = 0; s < SS; ++s) {
        const float* Hc = g_H[p];
        float* Hn = g_H[p ^ 1];
        const float* xpg = g_xproj + (size_t)s * BB * 3 * HD;

        // stage xproj loads early
        float2 xv1, xv2;
        {
            int b = tid >> 3, q = tid & 7;
            xv1 = __ldcs((const float2*)(xpg + b * 3 * HD + gate1 * HD + colb1 + q * 2));
        }
        if (tid < 256) {
            int b = tid >> 2, q = tid & 3;
            xv2 = __ldcs((const float2*)(xpg + b * 3 * HD + 2 * HD + colb2 + q * 2));
        }

        // ---------------- phase 1: r or z (16 cols, 64 k per warp) --------
        ull acc[4][4];
#pragma unroll
        for (int i = 0; i < 4; i++)
#pragma unroll
            for (int j = 0; j < 4; j++) acc[i][j] = 0ull;
        {
            const float* hptr = Hc + (w * 64) * BB + mg * 8;
            const float* wptr = W1 + (size_t)(w * 64) * HD + colb1 + cg * 4;
#pragma unroll 1
            for (int k = 0; k < 64; k += 8) {
#pragma unroll
                for (int u = 0; u < 8; ++u) {
                    ull h0, h1, h2, h3;
                    ldcg_2x64(hptr, h0, h1);
                    ldcg_2x64(hptr + 4, h2, h3);
                    float4 wv = __ldg((const float4*)wptr);
                    ull w0 = splat2(wv.x), w1 = splat2(wv.y);
                    ull w2 = splat2(wv.z), w3 = splat2(wv.w);
                    acc[0][0] = ffma2(h0, w0, acc[0][0]);
                    acc[0][1] = ffma2(h0, w1, acc[0][1]);
                    acc[0][2] = ffma2(h0, w2, acc[0][2]);
                    acc[0][3] = ffma2(h0, w3, acc[0][3]);
                    acc[1][0] = ffma2(h1, w0, acc[1][0]);
                    acc[1][1] = ffma2(h1, w1, acc[1][1]);
                    acc[1][2] = ffma2(h1, w2, acc[1][2]);
                    acc[1][3] = ffma2(h1, w3, acc[1][3]);
                    acc[2][0] = ffma2(h2, w0, acc[2][0]);
                    acc[2][1] = ffma2(h2, w1, acc[2][1]);
                    acc[2][2] = ffma2(h2, w2, acc[2][2]);
                    acc[2][3] = ffma2(h2, w3, acc[2][3]);
                    acc[3][0] = ffma2(h3, w0, acc[3][0]);
                    acc[3][1] = ffma2(h3, w1, acc[3][1]);
                    acc[3][2] = ffma2(h3, w2, acc[3][2]);
                    acc[3][3] = ffma2(h3, w3, acc[3][3]);
                    hptr += BB; wptr += HD;
                }
            }
        }
        // stage-1: warps 0-7 write lane-linear slots (conflict-free)
        if (w < 8) {
#pragma unroll
            for (int i = 0; i < 4; i++)
#pragma unroll
                for (int j = 0; j < 4; j++)
                    red[w][(i * 4 + j) * 32 + lane] = acc[i][j];
        }
        {
            int b = tid >> 3, q = tid & 7;
            *(float2*)&xp1[b * 18 + q * 2] = xv1;
        }
        if (tid < 256) {
            int b = tid >> 2, q = tid & 3;
            *(float2*)&xp2[b * 10 + q * 2] = xv2;
        }
        __syncthreads();
        if (w >= 8) {
#pragma unroll
            for (int i = 0; i < 4; i++)
#pragma unroll
                for (int j = 0; j < 4; j++) {
                    int slot = (i * 4 + j) * 32 + lane;
                    float2 a = unpack2(acc[i][j]);
                    float2 c = unpack2(red[w - 8][slot]);
                    a.x += c.x; a.y += c.y;
                    red[w - 8][slot] = *(ull*)&a;
                }
        }
        __syncthreads();

        // epilogue: thread t owns slot t (conflict-free gather over 8 banks)
        {
            const int t = tid;
            const int el = t & 31, q = t >> 5;
            const int ei = q >> 2, ej = q & 3;
            const int emg = el & 7, ecg = el >> 3;
            const int row = emg * 4 + ei;        // m-pair 0..31
            const int col = ecg * 4 + ej;        // 0..15
            float2 sum = make_float2(0.f, 0.f);
#pragma unroll
            for (int ww = 0; ww < 8; ++ww) {
                float2 v = unpack2(red[ww][t]);
                sum.x += v.x; sum.y += v.y;
            }
            const int mb = 2 * row;
            const int colg = colb1 + col;
            float v0 = sigmoid_f(sum.x + xp1[mb * 18 + col]);
            float v1 = sigmoid_f(sum.y + xp1[(mb + 1) * 18 + col]);
            if (gate1 == 0) {
                float2 hp = ldcg_f2(Hc + colg * BB + mb);
                *(float2*)(g_Hr + colg * BB + mb) = make_float2(hp.x * v0, hp.y * v1);
            } else {
                *(float2*)(g_Z + colg * BB + mb) = make_float2(v0, v1);
            }
        }
        grid_barrier(bar++, bx);

        // ---------------- phase 2: candidate h (8 cols) ----------------
        ull acc2[4][2];
#pragma unroll
        for (int i = 0; i < 4; i++) { acc2[i][0] = 0ull; acc2[i][1] = 0ull; }
        {
            const float* hptr = g_Hr + (w * 64) * BB + mg * 8;
            const float* wptr = Whc + (size_t)(w * 64) * HD + colb2 + cg * 2;
#pragma unroll 1
            for (int k = 0; k < 64; k += 8) {
#pragma unroll
                for (int u = 0; u < 8; ++u) {
                    ull h0, h1, h2, h3;
                    ldcg_2x64(hptr, h0, h1);
                    ldcg_2x64(hptr + 4, h2, h3);
                    float2 wv = __ldg((const float2*)wptr);
                    ull w0 = splat2(wv.x), w1 = splat2(wv.y);
                    acc2[0][0] = ffma2(h0, w0, acc2[0][0]);
                    acc2[0][1] = ffma2(h0, w1, acc2[0][1]);
                    acc2[1][0] = ffma2(h1, w0, acc2[1][0]);
                    acc2[1][1] = ffma2(h1, w1, acc2[1][1]);
                    acc2[2][0] = ffma2(h2, w0, acc2[2][0]);
                    acc2[2][1] = ffma2(h2, w1, acc2[2][1]);
                    acc2[3][0] = ffma2(h3, w0, acc2[3][0]);
                    acc2[3][1] = ffma2(h3, w1, acc2[3][1]);
                    hptr += BB; wptr += HD;
                }
            }
        }
        if (w < 8) {
#pragma unroll
            for (int i = 0; i < 4; i++)
#pragma unroll
                for (int j = 0; j < 2; j++)
                    red[w][(i * 2 + j) * 32 + lane] = acc2[i][j];
        }
        __syncthreads();
        if (w >= 8) {
#pragma unroll
            for (int i = 0; i < 4; i++)
#pragma unroll
                for (int j = 0; j < 2; j++) {
                    int slot = (i * 2 + j) * 32 + lane;
                    float2 a = unpack2(acc2[i][j]);
                    float2 c = unpack2(red[w - 8][slot]);
                    a.x += c.x; a.y += c.y;
                    red[w - 8][slot] = *(ull*)&a;
                }
        }
        __syncthreads();

        if (tid < 256) {
            const int t = tid;
            const int el = t & 31, q = t >> 5;
            const int ei = q >> 1, ej = q & 1;
            const int emg = el & 7, ecg = el >> 3;
            const int row = emg * 4 + ei;        // 0..31
            const int col = ecg * 2 + ej;        // 0..7
            float2 sum = make_float2(0.f, 0.f);
#pragma unroll
            for (int ww = 0; ww < 8; ++ww) {
                float2 v = unpack2(red[ww][t]);
                sum.x += v.x; sum.y += v.y;
            }
            const int mb = 2 * row;
            const int colg = colb2 + col;
            float h0 = tanh_f(sum.x + xp2[mb * 10 + col]);
            float h1 = tanh_f(sum.y + xp2[(mb + 1) * 10 + col]);
            float2 z  = ldcg_f2(g_Z + colg * BB + mb);
            float2 hp = ldcg_f2(Hc + colg * BB + mb);
            *(float2*)(Hn + colg * BB + mb) =
                make_float2(z.x * hp.x + (1.f - z.x) * h0,
                            z.y * hp.y + (1.f - z.y) * h1);
        }
        if (s != SS - 1) grid_barrier(bar++, bx);
        p ^= 1;
    }
}

// =====================================================================
// Kernel 3: logits + softmax
// =====================================================================
__global__ __launch_bounds__(128) void out_kernel(const float* __restrict__ Whq,
                                                  const float* __restrict__ bq,
                                                  float* __restrict__ out) {
    const int b = blockIdx.x;
    const int t = threadIdx.x;
    float acc[NO];
#pragma unroll
    for (int o = 0; o < NO; o++) acc[o] = 0.f;
    for (int k = t; k < HD; k += 128) {
        float hv = g_H[0][k * BB + b];
        const float* wp = Whq + (size_t)k * NO;
#pragma unroll
        for (int o = 0; o < NO; o++) acc[o] += hv * wp[o];
    }
    __shared__ float part[128 * NO];
#pragma unroll
    for (int o = 0; o < NO; o++) part[t * NO + o] = acc[o];
    __syncthreads();
    __shared__ float logits[NO];
    if (t < NO) {
        float sum = bq[t];
        for (int i = 0; i < 128; i++) sum += part[i * NO + t];
        logits[t] = sum;
    }
    __syncthreads();
    if (t == 0) {
        float mx = logits[0];
#pragma unroll
        for (int o = 1; o < NO; o++) mx = fmaxf(mx, logits[o]);
        float e[NO]; float sum = 0.f;
#pragma unroll
        for (int o = 0; o < NO; o++) { e[o] = __expf(logits[o] - mx); sum += e[o]; }
        float inv = 1.0f / sum;
#pragma unroll
        for (int o = 0; o < NO; o++) out[b * NO + o] = e[o] * inv;
    }
}

// =====================================================================
extern "C" void kernel_launch(void* const* d_in, const int* in_sizes, int n_in,
                              void* d_out, int out_size) {
    const int*   inputs = (const int*)d_in[0];
    const float* emb = (const float*)d_in[1];
    const float* Wxr = (const float*)d_in[2];
    const float* Whr = (const float*)d_in[3];
    const float* br  = (const float*)d_in[4];
    const float* Wxz = (const float*)d_in[5];
    const float* Whz = (const float*)d_in[6];
    const float* bz  = (const float*)d_in[7];
    const float* Wxc = (const float*)d_in[8];
    const float* Whc = (const float*)d_in[9];
    const float* bc  = (const float*)d_in[10];
    const float* Whq = (const float*)d_in[11];
    const float* bq  = (const float*)d_in[12];
    float* out = (float*)d_out;

    reset_kernel<<<1, 256>>>();
    dim3 pg(48, 512);
    proj_kernel<<<pg, 256>>>(inputs, emb, Wxr, Wxz, Wxc, br, bz, bc);
    gru_kernel<<<NBLK, GTHR>>>(Whr, Whz, Whc);
    out_kernel<<<64, 128>>>(Whq, bq, out);
}

// round 6
// speedup vs baseline: 3.2030x; 1.0432x over previous
#include <cuda_runtime.h>

#define BB 64
#define SS 512
#define EE 512
#define HD 1024
#define NO 10
#define NBLK 128
#define GTHR 512

typedef unsigned long long ull;

// -------- scratch --------
__device__ float g_xproj[(size_t)SS * BB * 3 * HD]; // [s][b][3072]
__device__ float g_H[2][HD * BB];                   // k-major [k][b]
__device__ float g_Hr[HD * BB];
__device__ unsigned g_arrive[NBLK * 32];            // 128B-strided arrive flags

// -------- packed f32x2 helpers --------
__device__ __forceinline__ ull ffma2(ull a, ull b, ull c) {
    ull d; asm("fma.rn.f32x2 %0, %1, %2, %3;" : "=l"(d) : "l"(a), "l"(b), "l"(c));
    return d;
}
__device__ __forceinline__ ull splat2(float x) {
    ull r; asm("mov.b64 %0, {%1,%1};" : "=l"(r) : "f"(x)); return r;
}
__device__ __forceinline__ float2 unpack2(ull v) {
    float2 f; asm("mov.b64 {%0,%1}, %2;" : "=f"(f.x), "=f"(f.y) : "l"(v)); return f;
}
__device__ __forceinline__ void ldcg_2x64(const float* p, ull& a, ull& b) {
    asm("ld.global.cg.v2.u64 {%0,%1}, [%2];" : "=l"(a), "=l"(b) : "l"(p));
}
__device__ __forceinline__ float2 ldcg_f2(const float* p) {
    float2 v; asm("ld.global.cg.v2.f32 {%0,%1}, [%2];" : "=f"(v.x), "=f"(v.y) : "l"(p));
    return v;
}
__device__ __forceinline__ float sigmoid_f(float x) {
    return 1.0f / (1.0f + __expf(-x));
}
__device__ __forceinline__ float tanh_f(float x) {
    float ax = fabsf(x);
    float t = __expf(-2.0f * ax);
    float r = __fdividef(1.0f - t, 1.0f + t);
    return copysignf(r, x);
}

// -------- flat grid barrier: every block polls all arrive flags --------
__device__ __forceinline__ void grid_barrier(unsigned target, int bx) {
    __syncthreads();
    if (threadIdx.x == 0) {
        __threadfence();
        asm volatile("st.release.gpu.u32 [%0], %1;"
                     :: "l"(&g_arrive[bx * 32]), "r"(target) : "memory");
    }
    if (threadIdx.x < NBLK) {
        const unsigned* p = &g_arrive[threadIdx.x * 32];
        unsigned v;
        do {
            asm volatile("ld.acquire.gpu.u32 %0, [%1];" : "=r"(v) : "l"(p) : "memory");
        } while (v < target);
    }
    __syncthreads();
}

__global__ void reset_kernel() {
    int t = threadIdx.x;
    for (int i = t; i < NBLK * 32; i += blockDim.x) g_arrive[i] = 0u;
}

// =====================================================================
// Kernel 1: input projection, double-buffered smem
// =====================================================================
__global__ __launch_bounds__(256) void proj_kernel(
    const int* __restrict__ inputs, const float* __restrict__ emb,
    const float* __restrict__ Wxr, const float* __restrict__ Wxz,
    const float* __restrict__ Wxc, const float* __restrict__ br,
    const float* __restrict__ bz, const float* __restrict__ bc) {
    const int s  = blockIdx.y;
    const int nt = blockIdx.x;
    const int gate = nt >> 4;
    const float* Wx   = (gate == 0) ? Wxr : ((gate == 1) ? Wxz : Wxc);
    const float* bias = (gate == 0) ? br  : ((gate == 1) ? bz  : bc);
    const int col0 = (nt & 15) * 64;

    __shared__ int tok[64];
    __shared__ __align__(16) float As[2][16][68];
    __shared__ __align__(16) float Bs[2][16][64];

    const int tid = threadIdx.x;
    if (tid < 64) tok[tid] = inputs[tid * SS + s];
    __syncthreads();

    const int tx = tid & 15, ty = tid >> 4;
    const int n0 = tx * 4, m0 = ty * 4;
    ull acc[4][2];
#pragma unroll
    for (int i = 0; i < 4; i++) { acc[i][0] = 0ull; acc[i][1] = 0ull; }

    const int lm = tid >> 2, lkq = tid & 3;
    const int bk = tid >> 4, bnq = tid & 15;

    const float* eptr = emb + (size_t)tok[lm] * EE + lkq * 4;
    {
        float4 av = *(const float4*)(eptr);
        float4 bv = *(const float4*)(Wx + (size_t)bk * HD + col0 + bnq * 4);
        As[0][lkq * 4 + 0][lm] = av.x;
        As[0][lkq * 4 + 1][lm] = av.y;
        As[0][lkq * 4 + 2][lm] = av.z;
        As[0][lkq * 4 + 3][lm] = av.w;
        *(float4*)&Bs[0][bk][bnq * 4] = bv;
    }
    __syncthreads();

    int p = 0;
#pragma unroll 1
    for (int k0 = 0; k0 < EE; k0 += 16) {
        float4 av_n, bv_n;
        const bool more = (k0 + 16 < EE);
        if (more) {
            av_n = *(const float4*)(eptr + k0 + 16);
            bv_n = *(const float4*)(Wx + (size_t)(k0 + 16 + bk) * HD + col0 + bnq * 4);
        }
#pragma unroll
        for (int kk = 0; kk < 16; ++kk) {
            float4 a4 = *(const float4*)&As[p][kk][m0];
            ulonglong2 b2 = *(const ulonglong2*)&Bs[p][kk][n0];
            ull aa;
            aa = splat2(a4.x);
            acc[0][0] = ffma2(aa, b2.x, acc[0][0]);
            acc[0][1] = ffma2(aa, b2.y, acc[0][1]);
            aa = splat2(a4.y);
            acc[1][0] = ffma2(aa, b2.x, acc[1][0]);
            acc[1][1] = ffma2(aa, b2.y, acc[1][1]);
            aa = splat2(a4.z);
            acc[2][0] = ffma2(aa, b2.x, acc[2][0]);
            acc[2][1] = ffma2(aa, b2.y, acc[2][1]);
            aa = splat2(a4.w);
            acc[3][0] = ffma2(aa, b2.x, acc[3][0]);
            acc[3][1] = ffma2(aa, b2.y, acc[3][1]);
        }
        if (more) {
            As[p ^ 1][lkq * 4 + 0][lm] = av_n.x;
            As[p ^ 1][lkq * 4 + 1][lm] = av_n.y;
            As[p ^ 1][lkq * 4 + 2][lm] = av_n.z;
            As[p ^ 1][lkq * 4 + 3][lm] = av_n.w;
            *(float4*)&Bs[p ^ 1][bk][bnq * 4] = bv_n;
            __syncthreads();
        }
        p ^= 1;
    }
    float4 bi = *(const float4*)(bias + col0 + n0);
#pragma unroll
    for (int i = 0; i < 4; i++) {
        float2 lo = unpack2(acc[i][0]), hi = unpack2(acc[i][1]);
        float4 v = make_float4(lo.x + bi.x, lo.y + bi.y, hi.x + bi.z, hi.y + bi.w);
        __stcs((float4*)(g_xproj + ((size_t)s * BB + m0 + i) * (3 * HD) + gate * HD + col0 + n0), v);
    }
}

// =====================================================================
// Kernel 2: persistent GRU. 128 blocks x 512 threads.
// Phase 1: block computes r AND z for ITS 8 phase-2 columns (16 col-slots:
//   slots 0-7 = r via Whr, slots 8-15 = z via Whz). z stays in smem.
// Phase 2: h-candidate + combine for the same 8 columns.
// =====================================================================
__global__ __launch_bounds__(GTHR, 1) void gru_kernel(
    const float* __restrict__ Whr, const float* __restrict__ Whz,
    const float* __restrict__ Whc) {
    __shared__ ull red[8][512];        // 32 KB, lane-linear slots
    __shared__ float xp1[64 * 18];     // staged xproj (r|z), row stride 18
    __shared__ float xp2[64 * 10];     // staged xproj (c), row stride 10
    __shared__ float zs[8 * 64];       // z values [col][b]

    const int tid = threadIdx.x, bx = blockIdx.x;
    const int w = tid >> 5, lane = tid & 31;
    const int mg = lane & 7;
    const int cg = lane >> 3;

    // zero-init H0 every launch
    {
        int idx = bx * GTHR + tid;
        if (idx < HD * BB / 4)
            ((float4*)g_H[0])[idx] = make_float4(0.f, 0.f, 0.f, 0.f);
    }
    unsigned bar = 1;
    grid_barrier(bar++, bx);

    const int colb = bx * 8;                       // this block's 8 columns
    // phase-1 weight base per thread: cg 0,1 -> Whr cols, cg 2,3 -> Whz cols
    const float* W1base = (cg < 2) ? Whr : Whz;
    const int w1col = colb + (cg & 1) * 4;

    // epilogue decode (phase 1): thread t -> slot t
    const int e_el = tid & 31, e_q = tid >> 5;
    const int e1_i = e_q >> 2, e1_j = e_q & 3;
    const int e1_row = (e_el & 7) * 4 + e1_i;      // m-pair 0..31
    const int e1_col = (e_el >> 3) * 4 + e1_j;     // 0..15 (0-7 r, 8-15 z)
    const int e1_mb = 2 * e1_row;
    // epilogue decode (phase 2): thread t (<256) -> slot t
    const int e2_i = e_q >> 1, e2_j = e_q & 1;
    const int e2_row = (e_el & 7) * 4 + e2_i;
    const int e2_col = (e_el >> 3) * 2 + e2_j;     // 0..7
    const int e2_mb = 2 * e2_row;

    int p = 0;
#pragma unroll 1
    for (int s = 0; s < SS; ++s) {
        const float* Hc = g_H[p];
        float* Hn = g_H[p ^ 1];
        const float* xpg = g_xproj + (size_t)s * BB * 3 * HD;

        // stage xproj loads early. xp1 slots: c<8 r-gate, c>=8 z-gate
        float2 xv1, xv2;
        {
            int b = tid >> 3, c2 = (tid & 7) * 2;
            const float* src = (c2 < 8)
                ? xpg + b * 3 * HD + 0 * HD + colb + c2
                : xpg + b * 3 * HD + 1 * HD + colb + (c2 - 8);
            xv1 = __ldcs((const float2*)src);
        }
        if (tid < 256) {
            int b = tid >> 2, q = tid & 3;
            xv2 = __ldcs((const float2*)(xpg + b * 3 * HD + 2 * HD + colb + q * 2));
        }
        // prefetch Hc pair for phase-1 r epilogue (stable during phase 1)
        float2 hc1;
        if (e1_col < 8) hc1 = ldcg_f2(Hc + (colb + e1_col) * BB + e1_mb);

        // ---------------- phase 1: r and z (16 col-slots, 64 k/warp) ------
        ull acc[4][4];
#pragma unroll
        for (int i = 0; i < 4; i++)
#pragma unroll
            for (int j = 0; j < 4; j++) acc[i][j] = 0ull;
        {
            const float* hptr = Hc + (w * 64) * BB + mg * 8;
            const float* wptr = W1base + (size_t)(w * 64) * HD + w1col;
#pragma unroll 1
            for (int k = 0; k < 64; k += 8) {
#pragma unroll
                for (int u = 0; u < 8; ++u) {
                    ull h0, h1, h2, h3;
                    ldcg_2x64(hptr, h0, h1);
                    ldcg_2x64(hptr + 4, h2, h3);
                    float4 wv = __ldg((const float4*)wptr);
                    ull w0 = splat2(wv.x), w1 = splat2(wv.y);
                    ull w2 = splat2(wv.z), w3 = splat2(wv.w);
                    acc[0][0] = ffma2(h0, w0, acc[0][0]);
                    acc[0][1] = ffma2(h0, w1, acc[0][1]);
                    acc[0][2] = ffma2(h0, w2, acc[0][2]);
                    acc[0][3] = ffma2(h0, w3, acc[0][3]);
                    acc[1][0] = ffma2(h1, w0, acc[1][0]);
                    acc[1][1] = ffma2(h1, w1, acc[1][1]);
                    acc[1][2] = ffma2(h1, w2, acc[1][2]);
                    acc[1][3] = ffma2(h1, w3, acc[1][3]);
                    acc[2][0] = ffma2(h2, w0, acc[2][0]);
                    acc[2][1] = ffma2(h2, w1, acc[2][1]);
                    acc[2][2] = ffma2(h2, w2, acc[2][2]);
                    acc[2][3] = ffma2(h2, w3, acc[2][3]);
                    acc[3][0] = ffma2(h3, w0, acc[3][0]);
                    acc[3][1] = ffma2(h3, w1, acc[3][1]);
                    acc[3][2] = ffma2(h3, w2, acc[3][2]);
                    acc[3][3] = ffma2(h3, w3, acc[3][3]);
                    hptr += BB; wptr += HD;
                }
            }
        }
        if (w < 8) {
#pragma unroll
            for (int i = 0; i < 4; i++)
#pragma unroll
                for (int j = 0; j < 4; j++)
                    red[w][(i * 4 + j) * 32 + lane] = acc[i][j];
        }
        {
            int b = tid >> 3, c2 = (tid & 7) * 2;
            *(float2*)&xp1[b * 18 + c2] = xv1;
        }
        if (tid < 256) {
            int b = tid >> 2, q = tid & 3;
            *(float2*)&xp2[b * 10 + q * 2] = xv2;
        }
        __syncthreads();
        if (w >= 8) {
#pragma unroll
            for (int i = 0; i < 4; i++)
#pragma unroll
                for (int j = 0; j < 4; j++) {
                    int slot = (i * 4 + j) * 32 + lane;
                    float2 a = unpack2(acc[i][j]);
                    float2 c = unpack2(red[w - 8][slot]);
                    a.x += c.x; a.y += c.y;
                    red[w - 8][slot] = *(ull*)&a;
                }
        }
        __syncthreads();

        // epilogue: slot t
        {
            float2 sum = make_float2(0.f, 0.f);
#pragma unroll
            for (int ww = 0; ww < 8; ++ww) {
                float2 v = unpack2(red[ww][tid]);
                sum.x += v.x; sum.y += v.y;
            }
            float v0 = sigmoid_f(sum.x + xp1[e1_mb * 18 + e1_col]);
            float v1 = sigmoid_f(sum.y + xp1[(e1_mb + 1) * 18 + e1_col]);
            if (e1_col < 8) {   // r: write Hr to global
                *(float2*)(g_Hr + (colb + e1_col) * BB + e1_mb) =
                    make_float2(hc1.x * v0, hc1.y * v1);
            } else {            // z: keep in smem
                *(float2*)&zs[(e1_col - 8) * 64 + e1_mb] = make_float2(v0, v1);
            }
        }
        grid_barrier(bar++, bx);

        // prefetch Hc pair for phase-2 combine
        float2 hc2;
        if (tid < 256) hc2 = ldcg_f2(Hc + (colb + e2_col) * BB + e2_mb);

        // ---------------- phase 2: candidate h (8 cols) ----------------
        ull acc2[4][2];
#pragma unroll
        for (int i = 0; i < 4; i++) { acc2[i][0] = 0ull; acc2[i][1] = 0ull; }
        {
            const float* hptr = g_Hr + (w * 64) * BB + mg * 8;
            const float* wptr = Whc + (size_t)(w * 64) * HD + colb + cg * 2;
#pragma unroll 1
            for (int k = 0; k < 64; k += 8) {
#pragma unroll
                for (int u = 0; u < 8; ++u) {
                    ull h0, h1, h2, h3;
                    ldcg_2x64(hptr, h0, h1);
                    ldcg_2x64(hptr + 4, h2, h3);
                    float2 wv = __ldg((const float2*)wptr);
                    ull w0 = splat2(wv.x), w1 = splat2(wv.y);
                    acc2[0][0] = ffma2(h0, w0, acc2[0][0]);
                    acc2[0][1] = ffma2(h0, w1, acc2[0][1]);
                    acc2[1][0] = ffma2(h1, w0, acc2[1][0]);
                    acc2[1][1] = ffma2(h1, w1, acc2[1][1]);
                    acc2[2][0] = ffma2(h2, w0, acc2[2][0]);
                    acc2[2][1] = ffma2(h2, w1, acc2[2][1]);
                    acc2[3][0] = ffma2(h3, w0, acc2[3][0]);
                    acc2[3][1] = ffma2(h3, w1, acc2[3][1]);
                    hptr += BB; wptr += HD;
                }
            }
        }
        if (w < 8) {
#pragma unroll
            for (int i = 0; i < 4; i++)
#pragma unroll
                for (int j = 0; j < 2; j++)
                    red[w][(i * 2 + j) * 32 + lane] = acc2[i][j];
        }
        __syncthreads();
        if (w >= 8) {
#pragma unroll
            for (int i = 0; i < 4; i++)
#pragma unroll
                for (int j = 0; j < 2; j++) {
                    int slot = (i * 2 + j) * 32 + lane;
                    float2 a = unpack2(acc2[i][j]);
                    float2 c = unpack2(red[w - 8][slot]);
                    a.x += c.x; a.y += c.y;
                    red[w - 8][slot] = *(ull*)&a;
                }
        }
        __syncthreads();

        if (tid < 256) {
            float2 sum = make_float2(0.f, 0.f);
#pragma unroll
            for (int ww = 0; ww < 8; ++ww) {
                float2 v = unpack2(red[ww][tid]);
                sum.x += v.x; sum.y += v.y;
            }
            float h0 = tanh_f(sum.x + xp2[e2_mb * 10 + e2_col]);
            float h1 = tanh_f(sum.y + xp2[(e2_mb + 1) * 10 + e2_col]);
            float2 z = *(const float2*)&zs[e2_col * 64 + e2_mb];
            *(float2*)(Hn + (colb + e2_col) * BB + e2_mb) =
                make_float2(z.x * hc2.x + (1.f - z.x) * h0,
                            z.y * hc2.y + (1.f - z.y) * h1);
        }
        if (s != SS - 1) grid_barrier(bar++, bx);
        p ^= 1;
    }
}

// =====================================================================
// Kernel 3: logits + softmax (256 threads)
// =====================================================================
__global__ __launch_bounds__(256) void out_kernel(const float* __restrict__ Whq,
                                                  const float* __restrict__ bq,
                                                  float* __restrict__ out) {
    const int b = blockIdx.x;
    const int t = threadIdx.x;
    float acc[NO];
#pragma unroll
    for (int o = 0; o < NO; o++) acc[o] = 0.f;
#pragma unroll
    for (int i = 0; i < HD / 256; i++) {
        int k = t + i * 256;
        float hv = g_H[0][k * BB + b];
        const float* wp = Whq + (size_t)k * NO;
#pragma unroll
        for (int o = 0; o < NO; o++) acc[o] += hv * wp[o];
    }
    __shared__ float part[256 * NO];
#pragma unroll
    for (int o = 0; o < NO; o++) part[t * NO + o] = acc[o];
    __syncthreads();
    __shared__ float logits[NO];
    if (t < NO) {
        float sum = bq[t];
        for (int i = 0; i < 256; i++) sum += part[i * NO + t];
        logits[t] = sum;
    }
    __syncthreads();
    if (t == 0) {
        float mx = logits[0];
#pragma unroll
        for (int o = 1; o < NO; o++) mx = fmaxf(mx, logits[o]);
        float e[NO]; float sum = 0.f;
#pragma unroll
        for (int o = 0; o < NO; o++) { e[o] = __expf(logits[o] - mx); sum += e[o]; }
        float inv = 1.0f / sum;
#pragma unroll
        for (int o = 0; o < NO; o++) out[b * NO + o] = e[o] * inv;
    }
}

// =====================================================================
extern "C" void kernel_launch(void* const* d_in, const int* in_sizes, int n_in,
                              void* d_out, int out_size) {
    const int*   inputs = (const int*)d_in[0];
    const float* emb = (const float*)d_in[1];
    const float* Wxr = (const float*)d_in[2];
    const float* Whr = (const float*)d_in[3];
    const float* br  = (const float*)d_in[4];
    const float* Wxz = (const float*)d_in[5];
    const float* Whz = (const float*)d_in[6];
    const float* bz  = (const float*)d_in[7];
    const float* Wxc = (const float*)d_in[8];
    const float* Whc = (const float*)d_in[9];
    const float* bc  = (const float*)d_in[10];
    const float* Whq = (const float*)d_in[11];
    const float* bq  = (const float*)d_in[12];
    float* out = (float*)d_out;

    reset_kernel<<<1, 256>>>();
    dim3 pg(48, 512);
    proj_kernel<<<pg, 256>>>(inputs, emb, Wxr, Wxz, Wxc, br, bz, bc);
    gru_kernel<<<NBLK, GTHR>>>(Whr, Whz, Whc);
    out_kernel<<<64, 256>>>(Whq, bq, out);
}

// round 7
// speedup vs baseline: 3.3139x; 1.0346x over previous
#include <cuda_runtime.h>

#define BB 64
#define SS 512
#define EE 512
#define HD 1024
#define NO 10
#define NBLK 128
#define GTHR 512

typedef unsigned long long ull;

// -------- scratch --------
__device__ float g_xproj[(size_t)SS * BB * 3 * HD]; // [s][b][3072]
__device__ float g_H[2][HD * BB];                   // k-major [k][b]
__device__ float g_Hr[HD * BB];
__device__ unsigned g_arrive[NBLK * 32];            // 128B-strided arrive flags

// -------- packed f32x2 helpers --------
__device__ __forceinline__ ull ffma2(ull a, ull b, ull c) {
    ull d; asm("fma.rn.f32x2 %0, %1, %2, %3;" : "=l"(d) : "l"(a), "l"(b), "l"(c));
    return d;
}
__device__ __forceinline__ ull splat2(float x) {
    ull r; asm("mov.b64 %0, {%1,%1};" : "=l"(r) : "f"(x)); return r;
}
__device__ __forceinline__ float2 unpack2(ull v) {
    float2 f; asm("mov.b64 {%0,%1}, %2;" : "=f"(f.x), "=f"(f.y) : "l"(v)); return f;
}
__device__ __forceinline__ void ldcg_2x64(const float* p, ull& a, ull& b) {
    asm("ld.global.cg.v2.u64 {%0,%1}, [%2];" : "=l"(a), "=l"(b) : "l"(p));
}
__device__ __forceinline__ float2 ldcg_f2(const float* p) {
    float2 v; asm("ld.global.cg.v2.f32 {%0,%1}, [%2];" : "=f"(v.x), "=f"(v.y) : "l"(p));
    return v;
}
__device__ __forceinline__ float sigmoid_f(float x) {
    return 1.0f / (1.0f + __expf(-x));
}
__device__ __forceinline__ float tanh_f(float x) {
    float ax = fabsf(x);
    float t = __expf(-2.0f * ax);
    float r = __fdividef(1.0f - t, 1.0f + t);
    return copysignf(r, x);
}

// -------- flat grid barrier with poll backoff --------
__device__ __forceinline__ void grid_barrier(unsigned target, int bx) {
    __syncthreads();
    if (threadIdx.x == 0) {
        // st.release.gpu orders all prior writes; no extra membar needed
        asm volatile("st.release.gpu.u32 [%0], %1;"
                     :: "l"(&g_arrive[bx * 32]), "r"(target) : "memory");
    }
    if (threadIdx.x < NBLK) {
        const unsigned* p = &g_arrive[threadIdx.x * 32];
        unsigned v;
        asm volatile("ld.acquire.gpu.u32 %0, [%1];" : "=r"(v) : "l"(p) : "memory");
        while (v < target) {
            __nanosleep(64);   // back off: don't flood L2 while others compute
            asm volatile("ld.acquire.gpu.u32 %0, [%1];" : "=r"(v) : "l"(p) : "memory");
        }
    }
    __syncthreads();
}

__global__ void reset_kernel() {
    int t = threadIdx.x;
    for (int i = t; i < NBLK * 32; i += blockDim.x) g_arrive[i] = 0u;
}

// =====================================================================
// Kernel 1: input projection, double-buffered smem
// =====================================================================
__global__ __launch_bounds__(256) void proj_kernel(
    const int* __restrict__ inputs, const float* __restrict__ emb,
    const float* __restrict__ Wxr, const float* __restrict__ Wxz,
    const float* __restrict__ Wxc, const float* __restrict__ br,
    const float* __restrict__ bz, const float* __restrict__ bc) {
    const int s  = blockIdx.y;
    const int nt = blockIdx.x;
    const int gate = nt >> 4;
    const float* Wx   = (gate == 0) ? Wxr : ((gate == 1) ? Wxz : Wxc);
    const float* bias = (gate == 0) ? br  : ((gate == 1) ? bz  : bc);
    const int col0 = (nt & 15) * 64;

    __shared__ int tok[64];
    __shared__ __align__(16) float As[2][16][68];
    __shared__ __align__(16) float Bs[2][16][64];

    const int tid = threadIdx.x;
    if (tid < 64) tok[tid] = inputs[tid * SS + s];
    __syncthreads();

    const int tx = tid & 15, ty = tid >> 4;
    const int n0 = tx * 4, m0 = ty * 4;
    ull acc[4][2];
#pragma unroll
    for (int i = 0; i < 4; i++) { acc[i][0] = 0ull; acc[i][1] = 0ull; }

    const int lm = tid >> 2, lkq = tid & 3;
    const int bk = tid >> 4, bnq = tid & 15;

    const float* eptr = emb + (size_t)tok[lm] * EE + lkq * 4;
    {
        float4 av = *(const float4*)(eptr);
        float4 bv = *(const float4*)(Wx + (size_t)bk * HD + col0 + bnq * 4);
        As[0][lkq * 4 + 0][lm] = av.x;
        As[0][lkq * 4 + 1][lm] = av.y;
        As[0][lkq * 4 + 2][lm] = av.z;
        As[0][lkq * 4 + 3][lm] = av.w;
        *(float4*)&Bs[0][bk][bnq * 4] = bv;
    }
    __syncthreads();

    int p = 0;
#pragma unroll 1
    for (int k0 = 0; k0 < EE; k0 += 16) {
        float4 av_n, bv_n;
        const bool more = (k0 + 16 < EE);
        if (more) {
            av_n = *(const float4*)(eptr + k0 + 16);
            bv_n = *(const float4*)(Wx + (size_t)(k0 + 16 + bk) * HD + col0 + bnq * 4);
        }
#pragma unroll
        for (int kk = 0; kk < 16; ++kk) {
            float4 a4 = *(const float4*)&As[p][kk][m0];
            ulonglong2 b2 = *(const ulonglong2*)&Bs[p][kk][n0];
            ull aa;
            aa = splat2(a4.x);
            acc[0][0] = ffma2(aa, b2.x, acc[0][0]);
            acc[0][1] = ffma2(aa, b2.y, acc[0][1]);
            aa = splat2(a4.y);
            acc[1][0] = ffma2(aa, b2.x, acc[1][0]);
            acc[1][1] = ffma2(aa, b2.y, acc[1][1]);
            aa = splat2(a4.z);
            acc[2][0] = ffma2(aa, b2.x, acc[2][0]);
            acc[2][1] = ffma2(aa, b2.y, acc[2][1]);
            aa = splat2(a4.w);
            acc[3][0] = ffma2(aa, b2.x, acc[3][0]);
            acc[3][1] = ffma2(aa, b2.y, acc[3][1]);
        }
        if (more) {
            As[p ^ 1][lkq * 4 + 0][lm] = av_n.x;
            As[p ^ 1][lkq * 4 + 1][lm] = av_n.y;
            As[p ^ 1][lkq * 4 + 2][lm] = av_n.z;
            As[p ^ 1][lkq * 4 + 3][lm] = av_n.w;
            *(float4*)&Bs[p ^ 1][bk][bnq * 4] = bv_n;
            __syncthreads();
        }
        p ^= 1;
    }
    float4 bi = *(const float4*)(bias + col0 + n0);
#pragma unroll
    for (int i = 0; i < 4; i++) {
        float2 lo = unpack2(acc[i][0]), hi = unpack2(acc[i][1]);
        float4 v = make_float4(lo.x + bi.x, lo.y + bi.y, hi.x + bi.z, hi.y + bi.w);
        __stcs((float4*)(g_xproj + ((size_t)s * BB + m0 + i) * (3 * HD) + gate * HD + col0 + n0), v);
    }
}

// =====================================================================
// Kernel 2: persistent GRU. 128 blocks x 512 threads.
// =====================================================================
__global__ __launch_bounds__(GTHR, 1) void gru_kernel(
    const float* __restrict__ Whr, const float* __restrict__ Whz,
    const float* __restrict__ Whc) {
    __shared__ ull red[8][512];        // 32 KB, lane-linear slots
    __shared__ float xp1[64 * 18];     // staged xproj (r|z)
    __shared__ float xp2[64 * 10];     // staged xproj (c)
    __shared__ float zs[8 * 64];       // z values [col][b]

    const int tid = threadIdx.x, bx = blockIdx.x;
    const int w = tid >> 5, lane = tid & 31;
    const int mg = lane & 7;
    const int cg = lane >> 3;

    // zero-init H0 every launch
    {
        int idx = bx * GTHR + tid;
        if (idx < HD * BB / 4)
            ((float4*)g_H[0])[idx] = make_float4(0.f, 0.f, 0.f, 0.f);
    }
    unsigned bar = 1;
    grid_barrier(bar++, bx);

    const int colb = bx * 8;
    const float* W1base = (cg < 2) ? Whr : Whz;
    const int w1col = colb + (cg & 1) * 4;

    // epilogue decode (phase 1)
    const int e_el = tid & 31, e_q = tid >> 5;
    const int e1_i = e_q >> 2, e1_j = e_q & 3;
    const int e1_row = (e_el & 7) * 4 + e1_i;
    const int e1_col = (e_el >> 3) * 4 + e1_j;     // 0..15 (0-7 r, 8-15 z)
    const int e1_mb = 2 * e1_row;
    // epilogue decode (phase 2)
    const int e2_i = e_q >> 1, e2_j = e_q & 1;
    const int e2_row = (e_el & 7) * 4 + e2_i;
    const int e2_col = (e_el >> 3) * 2 + e2_j;     // 0..7
    const int e2_mb = 2 * e2_row;

    int p = 0;
#pragma unroll 1
    for (int s = 0; s < SS; ++s) {
        const float* Hc = g_H[p];
        float* Hn = g_H[p ^ 1];
        const float* xpg = g_xproj + (size_t)s * BB * 3 * HD;

        // stage xproj loads early
        float2 xv1, xv2;
        {
            int b = tid >> 3, c2 = (tid & 7) * 2;
            const float* src = (c2 < 8)
                ? xpg + b * 3 * HD + 0 * HD + colb + c2
                : xpg + b * 3 * HD + 1 * HD + colb + (c2 - 8);
            xv1 = __ldcs((const float2*)src);
        }
        if (tid < 256) {
            int b = tid >> 2, q = tid & 3;
            xv2 = __ldcs((const float2*)(xpg + b * 3 * HD + 2 * HD + colb + q * 2));
        }
        // prefetch BOTH epilogue Hc pairs now (Hc stable all step)
        float2 hc1, hc2;
        if (e1_col < 8) hc1 = ldcg_f2(Hc + (colb + e1_col) * BB + e1_mb);
        if (tid < 256)  hc2 = ldcg_f2(Hc + (colb + e2_col) * BB + e2_mb);

        // ---------------- phase 1: r and z ----------------
        ull acc[4][4];
#pragma unroll
        for (int i = 0; i < 4; i++)
#pragma unroll
            for (int j = 0; j < 4; j++) acc[i][j] = 0ull;
        {
            const float* hptr = Hc + (w * 64) * BB + mg * 8;
            const float* wptr = W1base + (size_t)(w * 64) * HD + w1col;
#pragma unroll 1
            for (int k = 0; k < 64; k += 8) {
#pragma unroll
                for (int u = 0; u < 8; ++u) {
                    ull h0, h1, h2, h3;
                    ldcg_2x64(hptr, h0, h1);
                    ldcg_2x64(hptr + 4, h2, h3);
                    float4 wv = __ldg((const float4*)wptr);
                    ull w0 = splat2(wv.x), w1 = splat2(wv.y);
                    ull w2 = splat2(wv.z), w3 = splat2(wv.w);
                    acc[0][0] = ffma2(h0, w0, acc[0][0]);
                    acc[0][1] = ffma2(h0, w1, acc[0][1]);
                    acc[0][2] = ffma2(h0, w2, acc[0][2]);
                    acc[0][3] = ffma2(h0, w3, acc[0][3]);
                    acc[1][0] = ffma2(h1, w0, acc[1][0]);
                    acc[1][1] = ffma2(h1, w1, acc[1][1]);
                    acc[1][2] = ffma2(h1, w2, acc[1][2]);
                    acc[1][3] = ffma2(h1, w3, acc[1][3]);
                    acc[2][0] = ffma2(h2, w0, acc[2][0]);
                    acc[2][1] = ffma2(h2, w1, acc[2][1]);
                    acc[2][2] = ffma2(h2, w2, acc[2][2]);
                    acc[2][3] = ffma2(h2, w3, acc[2][3]);
                    acc[3][0] = ffma2(h3, w0, acc[3][0]);
                    acc[3][1] = ffma2(h3, w1, acc[3][1]);
                    acc[3][2] = ffma2(h3, w2, acc[3][2]);
                    acc[3][3] = ffma2(h3, w3, acc[3][3]);
                    hptr += BB; wptr += HD;
                }
            }
        }
        if (w < 8) {
#pragma unroll
            for (int i = 0; i < 4; i++)
#pragma unroll
                for (int j = 0; j < 4; j++)
                    red[w][(i * 4 + j) * 32 + lane] = acc[i][j];
        }
        {
            int b = tid >> 3, c2 = (tid & 7) * 2;
            *(float2*)&xp1[b * 18 + c2] = xv1;
        }
        if (tid < 256) {
            int b = tid >> 2, q = tid & 3;
            *(float2*)&xp2[b * 10 + q * 2] = xv2;
        }
        __syncthreads();
        if (w >= 8) {
#pragma unroll
            for (int i = 0; i < 4; i++)
#pragma unroll
                for (int j = 0; j < 4; j++) {
                    int slot = (i * 4 + j) * 32 + lane;
                    float2 a = unpack2(acc[i][j]);
                    float2 c = unpack2(red[w - 8][slot]);
                    a.x += c.x; a.y += c.y;
                    red[w - 8][slot] = *(ull*)&a;
                }
        }
        __syncthreads();

        {
            float2 sum = make_float2(0.f, 0.f);
#pragma unroll
            for (int ww = 0; ww < 8; ++ww) {
                float2 v = unpack2(red[ww][tid]);
                sum.x += v.x; sum.y += v.y;
            }
            float v0 = sigmoid_f(sum.x + xp1[e1_mb * 18 + e1_col]);
            float v1 = sigmoid_f(sum.y + xp1[(e1_mb + 1) * 18 + e1_col]);
            if (e1_col < 8) {
                *(float2*)(g_Hr + (colb + e1_col) * BB + e1_mb) =
                    make_float2(hc1.x * v0, hc1.y * v1);
            } else {
                *(float2*)&zs[(e1_col - 8) * 64 + e1_mb] = make_float2(v0, v1);
            }
        }
        grid_barrier(bar++, bx);

        // ---------------- phase 2: candidate h ----------------
        ull acc2[4][2];
#pragma unroll
        for (int i = 0; i < 4; i++) { acc2[i][0] = 0ull; acc2[i][1] = 0ull; }
        {
            const float* hptr = g_Hr + (w * 64) * BB + mg * 8;
            const float* wptr = Whc + (size_t)(w * 64) * HD + colb + cg * 2;
#pragma unroll 1
            for (int k = 0; k < 64; k += 8) {
#pragma unroll
                for (int u = 0; u < 8; ++u) {
                    ull h0, h1, h2, h3;
                    ldcg_2x64(hptr, h0, h1);
                    ldcg_2x64(hptr + 4, h2, h3);
                    float2 wv = __ldg((const float2*)wptr);
                    ull w0 = splat2(wv.x), w1 = splat2(wv.y);
                    acc2[0][0] = ffma2(h0, w0, acc2[0][0]);
                    acc2[0][1] = ffma2(h0, w1, acc2[0][1]);
                    acc2[1][0] = ffma2(h1, w0, acc2[1][0]);
                    acc2[1][1] = ffma2(h1, w1, acc2[1][1]);
                    acc2[2][0] = ffma2(h2, w0, acc2[2][0]);
                    acc2[2][1] = ffma2(h2, w1, acc2[2][1]);
                    acc2[3][0] = ffma2(h3, w0, acc2[3][0]);
                    acc2[3][1] = ffma2(h3, w1, acc2[3][1]);
                    hptr += BB; wptr += HD;
                }
            }
        }
        if (w < 8) {
#pragma unroll
            for (int i = 0; i < 4; i++)
#pragma unroll
                for (int j = 0; j < 2; j++)
                    red[w][(i * 2 + j) * 32 + lane] = acc2[i][j];
        }
        __syncthreads();
        if (w >= 8) {
#pragma unroll
            for (int i = 0; i < 4; i++)
#pragma unroll
                for (int j = 0; j < 2; j++) {
                    int slot = (i * 2 + j) * 32 + lane;
                    float2 a = unpack2(acc2[i][j]);
                    float2 c = unpack2(red[w - 8][slot]);
                    a.x += c.x; a.y += c.y;
                    red[w - 8][slot] = *(ull*)&a;
                }
        }
        __syncthreads();

        if (tid < 256) {
            float2 sum = make_float2(0.f, 0.f);
#pragma unroll
            for (int ww = 0; ww < 8; ++ww) {
                float2 v = unpack2(red[ww][tid]);
                sum.x += v.x; sum.y += v.y;
            }
            float h0 = tanh_f(sum.x + xp2[e2_mb * 10 + e2_col]);
            float h1 = tanh_f(sum.y + xp2[(e2_mb + 1) * 10 + e2_col]);
            float2 z = *(const float2*)&zs[e2_col * 64 + e2_mb];
            *(float2*)(Hn + (colb + e2_col) * BB + e2_mb) =
                make_float2(z.x * hc2.x + (1.f - z.x) * h0,
                            z.y * hc2.y + (1.f - z.y) * h1);
        }
        if (s != SS - 1) grid_barrier(bar++, bx);
        p ^= 1;
    }
}

// =====================================================================
// Kernel 3: logits + softmax (256 threads)
// =====================================================================
__global__ __launch_bounds__(256) void out_kernel(const float* __restrict__ Whq,
                                                  const float* __restrict__ bq,
                                                  float* __restrict__ out) {
    const int b = blockIdx.x;
    const int t = threadIdx.x;
    float acc[NO];
#pragma unroll
    for (int o = 0; o < NO; o++) acc[o] = 0.f;
#pragma unroll
    for (int i = 0; i < HD / 256; i++) {
        int k = t + i * 256;
        float hv = g_H[0][k * BB + b];
        const float* wp = Whq + (size_t)k * NO;
#pragma unroll
        for (int o = 0; o < NO; o++) acc[o] += hv * wp[o];
    }
    __shared__ float part[256 * NO];
#pragma unroll
    for (int o = 0; o < NO; o++) part[t * NO + o] = acc[o];
    __syncthreads();
    __shared__ float logits[NO];
    if (t < NO) {
        float sum = bq[t];
        for (int i = 0; i < 256; i++) sum += part[i * NO + t];
        logits[t] = sum;
    }
    __syncthreads();
    if (t == 0) {
        float mx = logits[0];
#pragma unroll
        for (int o = 1; o < NO; o++) mx = fmaxf(mx, logits[o]);
        float e[NO]; float sum = 0.f;
#pragma unroll
        for (int o = 0; o < NO; o++) { e[o] = __expf(logits[o] - mx); sum += e[o]; }
        float inv = 1.0f / sum;
#pragma unroll
        for (int o = 0; o < NO; o++) out[b * NO + o] = e[o] * inv;
    }
}

// =====================================================================
extern "C" void kernel_launch(void* const* d_in, const int* in_sizes, int n_in,
                              void* d_out, int out_size) {
    const int*   inputs = (const int*)d_in[0];
    const float* emb = (const float*)d_in[1];
    const float* Wxr = (const float*)d_in[2];
    const float* Whr = (const float*)d_in[3];
    const float* br  = (const float*)d_in[4];
    const float* Wxz = (const float*)d_in[5];
    const float* Whz = (const float*)d_in[6];
    const float* bz  = (const float*)d_in[7];
    const float* Wxc = (const float*)d_in[8];
    const float* Whc = (const float*)d_in[9];
    const float* bc  = (const float*)d_in[10];
    const float* Whq = (const float*)d_in[11];
    const float* bq  = (const float*)d_in[12];
    float* out = (float*)d_out;

    reset_kernel<<<1, 256>>>();
    dim3 pg(48, 512);
    proj_kernel<<<pg, 256>>>(inputs, emb, Wxr, Wxz, Wxc, br, bz, bc);
    gru_kernel<<<NBLK, GTHR>>>(Whr, Whz, Whc);
    out_kernel<<<64, 256>>>(Whq, bq, out);
}

// round 8
// speedup vs baseline: 3.3663x; 1.0158x over previous
#include <cuda_runtime.h>

#define BB 64
#define SS 512
#define EE 512
#define HD 1024
#define NO 10
#define NBLK 128
#define GTHR 512

typedef unsigned long long ull;

// -------- scratch --------
__device__ float g_xproj[(size_t)SS * BB * 3 * HD]; // [s][b][3072]
__device__ float g_H[2][HD * BB];                   // k-major [k][b]
__device__ float g_Hr[2][HD * BB];                  // double-buffered by step parity
__device__ unsigned g_arrive[NBLK * 32];            // flat init barrier
__device__ unsigned g_F1[NBLK * 32];                // phase-1 done flags (step+1)
__device__ unsigned g_F2[NBLK * 32];                // phase-2 done flags (step+1)

// -------- packed f32x2 helpers --------
__device__ __forceinline__ ull ffma2(ull a, ull b, ull c) {
    ull d; asm("fma.rn.f32x2 %0, %1, %2, %3;" : "=l"(d) : "l"(a), "l"(b), "l"(c));
    return d;
}
__device__ __forceinline__ ull splat2(float x) {
    ull r; asm("mov.b64 %0, {%1,%1};" : "=l"(r) : "f"(x)); return r;
}
__device__ __forceinline__ float2 unpack2(ull v) {
    float2 f; asm("mov.b64 {%0,%1}, %2;" : "=f"(f.x), "=f"(f.y) : "l"(v)); return f;
}
__device__ __forceinline__ void ldcg_2x64(const float* p, ull& a, ull& b) {
    asm("ld.global.cg.v2.u64 {%0,%1}, [%2];" : "=l"(a), "=l"(b) : "l"(p));
}
__device__ __forceinline__ float2 ldcg_f2(const float* p) {
    float2 v; asm("ld.global.cg.v2.f32 {%0,%1}, [%2];" : "=f"(v.x), "=f"(v.y) : "l"(p));
    return v;
}
__device__ __forceinline__ float sigmoid_f(float x) {
    return 1.0f / (1.0f + __expf(-x));
}
__device__ __forceinline__ float tanh_f(float x) {
    float ax = fabsf(x);
    float t = __expf(-2.0f * ax);
    float r = __fdividef(1.0f - t, 1.0f + t);
    return copysignf(r, x);
}

// wait: lanes 0-7 of the warp each poll one producer flag
__device__ __forceinline__ void warp_wait_flags(const unsigned* F, int w,
                                                unsigned target, int lane) {
    if (lane < 8) {
        const unsigned* p = F + (w * 8 + lane) * 32;
        unsigned v;
        asm volatile("ld.acquire.gpu.u32 %0, [%1];" : "=r"(v) : "l"(p) : "memory");
        while (v < target) {
            __nanosleep(32);
            asm volatile("ld.acquire.gpu.u32 %0, [%1];" : "=r"(v) : "l"(p) : "memory");
        }
    }
    __syncwarp();
}

__device__ __forceinline__ void publish(unsigned* slot, unsigned val) {
    asm volatile("st.release.gpu.u32 [%0], %1;" :: "l"(slot), "r"(val) : "memory");
}

// flat barrier (used once, after H0 init)
__device__ __forceinline__ void flat_barrier(unsigned target, int bx) {
    __syncthreads();
    if (threadIdx.x == 0) {
        __threadfence();
        publish(&g_arrive[bx * 32], target);
    }
    if (threadIdx.x < NBLK) {
        const unsigned* p = &g_arrive[threadIdx.x * 32];
        unsigned v;
        do {
            asm volatile("ld.acquire.gpu.u32 %0, [%1];" : "=r"(v) : "l"(p) : "memory");
        } while (v < target);
    }
    __syncthreads();
}

__global__ void reset_kernel() {
    int t = threadIdx.x;
    for (int i = t; i < NBLK * 32; i += blockDim.x) {
        g_arrive[i] = 0u; g_F1[i] = 0u; g_F2[i] = 0u;
    }
}

// =====================================================================
// Kernel 1: input projection (unchanged)
// =====================================================================
__global__ __launch_bounds__(256) void proj_kernel(
    const int* __restrict__ inputs, const float* __restrict__ emb,
    const float* __restrict__ Wxr, const float* __restrict__ Wxz,
    const float* __restrict__ Wxc, const float* __restrict__ br,
    const float* __restrict__ bz, const float* __restrict__ bc) {
    const int s  = blockIdx.y;
    const int nt = blockIdx.x;
    const int gate = nt >> 4;
    const float* Wx   = (gate == 0) ? Wxr : ((gate == 1) ? Wxz : Wxc);
    const float* bias = (gate == 0) ? br  : ((gate == 1) ? bz  : bc);
    const int col0 = (nt & 15) * 64;

    __shared__ int tok[64];
    __shared__ __align__(16) float As[2][16][68];
    __shared__ __align__(16) float Bs[2][16][64];

    const int tid = threadIdx.x;
    if (tid < 64) tok[tid] = inputs[tid * SS + s];
    __syncthreads();

    const int tx = tid & 15, ty = tid >> 4;
    const int n0 = tx * 4, m0 = ty * 4;
    ull acc[4][2];
#pragma unroll
    for (int i = 0; i < 4; i++) { acc[i][0] = 0ull; acc[i][1] = 0ull; }

    const int lm = tid >> 2, lkq = tid & 3;
    const int bk = tid >> 4, bnq = tid & 15;

    const float* eptr = emb + (size_t)tok[lm] * EE + lkq * 4;
    {
        float4 av = *(const float4*)(eptr);
        float4 bv = *(const float4*)(Wx + (size_t)bk * HD + col0 + bnq * 4);
        As[0][lkq * 4 + 0][lm] = av.x;
        As[0][lkq * 4 + 1][lm] = av.y;
        As[0][lkq * 4 + 2][lm] = av.z;
        As[0][lkq * 4 + 3][lm] = av.w;
        *(float4*)&Bs[0][bk][bnq * 4] = bv;
    }
    __syncthreads();

    int p = 0;
#pragma unroll 1
    for (int k0 = 0; k0 < EE; k0 += 16) {
        float4 av_n, bv_n;
        const bool more = (k0 + 16 < EE);
        if (more) {
            av_n = *(const float4*)(eptr + k0 + 16);
            bv_n = *(const float4*)(Wx + (size_t)(k0 + 16 + bk) * HD + col0 + bnq * 4);
        }
#pragma unroll
        for (int kk = 0; kk < 16; ++kk) {
            float4 a4 = *(const float4*)&As[p][kk][m0];
            ulonglong2 b2 = *(const ulonglong2*)&Bs[p][kk][n0];
            ull aa;
            aa = splat2(a4.x);
            acc[0][0] = ffma2(aa, b2.x, acc[0][0]);
            acc[0][1] = ffma2(aa, b2.y, acc[0][1]);
            aa = splat2(a4.y);
            acc[1][0] = ffma2(aa, b2.x, acc[1][0]);
            acc[1][1] = ffma2(aa, b2.y, acc[1][1]);
            aa = splat2(a4.z);
            acc[2][0] = ffma2(aa, b2.x, acc[2][0]);
            acc[2][1] = ffma2(aa, b2.y, acc[2][1]);
            aa = splat2(a4.w);
            acc[3][0] = ffma2(aa, b2.x, acc[3][0]);
            acc[3][1] = ffma2(aa, b2.y, acc[3][1]);
        }
        if (more) {
            As[p ^ 1][lkq * 4 + 0][lm] = av_n.x;
            As[p ^ 1][lkq * 4 + 1][lm] = av_n.y;
            As[p ^ 1][lkq * 4 + 2][lm] = av_n.z;
            As[p ^ 1][lkq * 4 + 3][lm] = av_n.w;
            *(float4*)&Bs[p ^ 1][bk][bnq * 4] = bv_n;
            __syncthreads();
        }
        p ^= 1;
    }
    float4 bi = *(const float4*)(bias + col0 + n0);
#pragma unroll
    for (int i = 0; i < 4; i++) {
        float2 lo = unpack2(acc[i][0]), hi = unpack2(acc[i][1]);
        float4 v = make_float4(lo.x + bi.x, lo.y + bi.y, hi.x + bi.z, hi.y + bi.w);
        __stcs((float4*)(g_xproj + ((size_t)s * BB + m0 + i) * (3 * HD) + gate * HD + col0 + n0), v);
    }
}

// =====================================================================
// Kernel 2: persistent GRU, dataflow-synchronized (no global barriers).
// =====================================================================
__global__ __launch_bounds__(GTHR, 1) void gru_kernel(
    const float* __restrict__ Whr, const float* __restrict__ Whz,
    const float* __restrict__ Whc) {
    __shared__ ull red[8][512];
    __shared__ float xp1[64 * 18];
    __shared__ float xp2[64 * 10];
    __shared__ float zs[8 * 64];

    const int tid = threadIdx.x, bx = blockIdx.x;
    const int w = tid >> 5, lane = tid & 31;
    const int mg = lane & 7;
    const int cg = lane >> 3;

    // zero-init H0 every launch
    {
        int idx = bx * GTHR + tid;
        if (idx < HD * BB / 4)
            ((float4*)g_H[0])[idx] = make_float4(0.f, 0.f, 0.f, 0.f);
    }
    flat_barrier(1, bx);

    const int colb = bx * 8;
    const float* W1base = (cg < 2) ? Whr : Whz;
    const int w1col = colb + (cg & 1) * 4;

    const int e_el = tid & 31, e_q = tid >> 5;
    const int e1_i = e_q >> 2, e1_j = e_q & 3;
    const int e1_row = (e_el & 7) * 4 + e1_i;
    const int e1_col = (e_el >> 3) * 4 + e1_j;     // 0..15 (0-7 r, 8-15 z)
    const int e1_mb = 2 * e1_row;
    const int e2_i = e_q >> 1, e2_j = e_q & 1;
    const int e2_row = (e_el & 7) * 4 + e2_i;
    const int e2_col = (e_el >> 3) * 2 + e2_j;     // 0..7
    const int e2_mb = 2 * e2_row;

    int p = 0;
#pragma unroll 1
    for (int s = 0; s < SS; ++s) {
        const float* Hc = g_H[p];
        float* Hn = g_H[p ^ 1];
        float* Hrbuf = g_Hr[s & 1];
        const float* xpg = g_xproj + (size_t)s * BB * 3 * HD;

        // prefetches (own-column data + xproj: no cross-block dependency)
        float2 xv1, xv2;
        {
            int b = tid >> 3, c2 = (tid & 7) * 2;
            const float* src = (c2 < 8)
                ? xpg + b * 3 * HD + 0 * HD + colb + c2
                : xpg + b * 3 * HD + 1 * HD + colb + (c2 - 8);
            xv1 = __ldcs((const float2*)src);
        }
        if (tid < 256) {
            int b = tid >> 2, q = tid & 3;
            xv2 = __ldcs((const float2*)(xpg + b * 3 * HD + 2 * HD + colb + q * 2));
        }
        float2 hc1, hc2;
        if (e1_col < 8) hc1 = ldcg_f2(Hc + (colb + e1_col) * BB + e1_mb);
        if (tid < 256)  hc2 = ldcg_f2(Hc + (colb + e2_col) * BB + e2_mb);

        // wait for my k-slice producers of H (phase-2 of step s-1)
        warp_wait_flags(g_F2, w, (unsigned)s, lane);

        // ---------------- phase 1: r and z ----------------
        ull acc[4][4];
#pragma unroll
        for (int i = 0; i < 4; i++)
#pragma unroll
            for (int j = 0; j < 4; j++) acc[i][j] = 0ull;
        {
            const float* hptr = Hc + (w * 64) * BB + mg * 8;
            const float* wptr = W1base + (size_t)(w * 64) * HD + w1col;
#pragma unroll 1
            for (int k = 0; k < 64; k += 8) {
#pragma unroll
                for (int u = 0; u < 8; ++u) {
                    ull h0, h1, h2, h3;
                    ldcg_2x64(hptr, h0, h1);
                    ldcg_2x64(hptr + 4, h2, h3);
                    float4 wv = __ldg((const float4*)wptr);
                    ull w0 = splat2(wv.x), w1 = splat2(wv.y);
                    ull w2 = splat2(wv.z), w3 = splat2(wv.w);
                    acc[0][0] = ffma2(h0, w0, acc[0][0]);
                    acc[0][1] = ffma2(h0, w1, acc[0][1]);
                    acc[0][2] = ffma2(h0, w2, acc[0][2]);
                    acc[0][3] = ffma2(h0, w3, acc[0][3]);
                    acc[1][0] = ffma2(h1, w0, acc[1][0]);
                    acc[1][1] = ffma2(h1, w1, acc[1][1]);
                    acc[1][2] = ffma2(h1, w2, acc[1][2]);
                    acc[1][3] = ffma2(h1, w3, acc[1][3]);
                    acc[2][0] = ffma2(h2, w0, acc[2][0]);
                    acc[2][1] = ffma2(h2, w1, acc[2][1]);
                    acc[2][2] = ffma2(h2, w2, acc[2][2]);
                    acc[2][3] = ffma2(h2, w3, acc[2][3]);
                    acc[3][0] = ffma2(h3, w0, acc[3][0]);
                    acc[3][1] = ffma2(h3, w1, acc[3][1]);
                    acc[3][2] = ffma2(h3, w2, acc[3][2]);
                    acc[3][3] = ffma2(h3, w3, acc[3][3]);
                    hptr += BB; wptr += HD;
                }
            }
        }
        if (w < 8) {
#pragma unroll
            for (int i = 0; i < 4; i++)
#pragma unroll
                for (int j = 0; j < 4; j++)
                    red[w][(i * 4 + j) * 32 + lane] = acc[i][j];
        }
        {
            int b = tid >> 3, c2 = (tid & 7) * 2;
            *(float2*)&xp1[b * 18 + c2] = xv1;
        }
        if (tid < 256) {
            int b = tid >> 2, q = tid & 3;
            *(float2*)&xp2[b * 10 + q * 2] = xv2;
        }
        __syncthreads();
        if (w >= 8) {
#pragma unroll
            for (int i = 0; i < 4; i++)
#pragma unroll
                for (int j = 0; j < 4; j++) {
                    int slot = (i * 4 + j) * 32 + lane;
                    float2 a = unpack2(acc[i][j]);
                    float2 c = unpack2(red[w - 8][slot]);
                    a.x += c.x; a.y += c.y;
                    red[w - 8][slot] = *(ull*)&a;
                }
        }
        __syncthreads();

        {
            float2 sum = make_float2(0.f, 0.f);
#pragma unroll
            for (int ww = 0; ww < 8; ++ww) {
                float2 v = unpack2(red[ww][tid]);
                sum.x += v.x; sum.y += v.y;
            }
            float v0 = sigmoid_f(sum.x + xp1[e1_mb * 18 + e1_col]);
            float v1 = sigmoid_f(sum.y + xp1[(e1_mb + 1) * 18 + e1_col]);
            if (e1_col < 8) {
                *(float2*)(Hrbuf + (colb + e1_col) * BB + e1_mb) =
                    make_float2(hc1.x * v0, hc1.y * v1);
            } else {
                *(float2*)&zs[(e1_col - 8) * 64 + e1_mb] = make_float2(v0, v1);
            }
        }
        __syncthreads();
        if (tid == 0) {
            __threadfence();
            publish(&g_F1[bx * 32], (unsigned)(s + 1));
        }

        // wait for my k-slice producers of Hr (phase-1 of step s)
        warp_wait_flags(g_F1, w, (unsigned)(s + 1), lane);

        // ---------------- phase 2: candidate h ----------------
        ull acc2[4][2];
#pragma unroll
        for (int i = 0; i < 4; i++) { acc2[i][0] = 0ull; acc2[i][1] = 0ull; }
        {
            const float* hptr = Hrbuf + (w * 64) * BB + mg * 8;
            const float* wptr = Whc + (size_t)(w * 64) * HD + colb + cg * 2;
#pragma unroll 1
            for (int k = 0; k < 64; k += 8) {
#pragma unroll
                for (int u = 0; u < 8; ++u) {
                    ull h0, h1, h2, h3;
                    ldcg_2x64(hptr, h0, h1);
                    ldcg_2x64(hptr + 4, h2, h3);
                    float2 wv = __ldg((const float2*)wptr);
                    ull w0 = splat2(wv.x), w1 = splat2(wv.y);
                    acc2[0][0] = ffma2(h0, w0, acc2[0][0]);
                    acc2[0][1] = ffma2(h0, w1, acc2[0][1]);
                    acc2[1][0] = ffma2(h1, w0, acc2[1][0]);
                    acc2[1][1] = ffma2(h1, w1, acc2[1][1]);
                    acc2[2][0] = ffma2(h2, w0, acc2[2][0]);
                    acc2[2][1] = ffma2(h2, w1, acc2[2][1]);
                    acc2[3][0] = ffma2(h3, w0, acc2[3][0]);
                    acc2[3][1] = ffma2(h3, w1, acc2[3][1]);
                    hptr += BB; wptr += HD;
                }
            }
        }
        if (w < 8) {
#pragma unroll
            for (int i = 0; i < 4; i++)
#pragma unroll
                for (int j = 0; j < 2; j++)
                    red[w][(i * 2 + j) * 32 + lane] = acc2[i][j];
        }
        __syncthreads();
        if (w >= 8) {
#pragma unroll
            for (int i = 0; i < 4; i++)
#pragma unroll
                for (int j = 0; j < 2; j++) {
                    int slot = (i * 2 + j) * 32 + lane;
                    float2 a = unpack2(acc2[i][j]);
                    float2 c = unpack2(red[w - 8][slot]);
                    a.x += c.x; a.y += c.y;
                    red[w - 8][slot] = *(ull*)&a;
                }
        }
        __syncthreads();

        if (tid < 256) {
            float2 sum = make_float2(0.f, 0.f);
#pragma unroll
            for (int ww = 0; ww < 8; ++ww) {
                float2 v = unpack2(red[ww][tid]);
                sum.x += v.x; sum.y += v.y;
            }
            float h0 = tanh_f(sum.x + xp2[e2_mb * 10 + e2_col]);
            float h1 = tanh_f(sum.y + xp2[(e2_mb + 1) * 10 + e2_col]);
            float2 z = *(const float2*)&zs[e2_col * 64 + e2_mb];
            *(float2*)(Hn + (colb + e2_col) * BB + e2_mb) =
                make_float2(z.x * hc2.x + (1.f - z.x) * h0,
                            z.y * hc2.y + (1.f - z.y) * h1);
        }
        __syncthreads();
        if (tid == 0) {
            __threadfence();
            publish(&g_F2[bx * 32], (unsigned)(s + 1));
        }
        p ^= 1;
    }
}

// =====================================================================
// Kernel 3: logits + softmax
// =====================================================================
__global__ __launch_bounds__(256) void out_kernel(const float* __restrict__ Whq,
                                                  const float* __restrict__ bq,
                                                  float* __restrict__ out) {
    const int b = blockIdx.x;
    const int t = threadIdx.x;
    float acc[NO];
#pragma unroll
    for (int o = 0; o < NO; o++) acc[o] = 0.f;
#pragma unroll
    for (int i = 0; i < HD / 256; i++) {
        int k = t + i * 256;
        float hv = g_H[0][k * BB + b];
        const float* wp = Whq + (size_t)k * NO;
#pragma unroll
        for (int o = 0; o < NO; o++) acc[o] += hv * wp[o];
    }
    __shared__ float part[256 * NO];
#pragma unroll
    for (int o = 0; o < NO; o++) part[t * NO + o] = acc[o];
    __syncthreads();
    __shared__ float logits[NO];
    if (t < NO) {
        float sum = bq[t];
        for (int i = 0; i < 256; i++) sum += part[i * NO + t];
        logits[t] = sum;
    }
    __syncthreads();
    if (t == 0) {
        float mx = logits[0];
#pragma unroll
        for (int o = 1; o < NO; o++) mx = fmaxf(mx, logits[o]);
        float e[NO]; float sum = 0.f;
#pragma unroll
        for (int o = 0; o < NO; o++) { e[o] = __expf(logits[o] - mx); sum += e[o]; }
        float inv = 1.0f / sum;
#pragma unroll
        for (int o = 0; o < NO; o++) out[b * NO + o] = e[o] * inv;
    }
}

// =====================================================================
extern "C" void kernel_launch(void* const* d_in, const int* in_sizes, int n_in,
                              void* d_out, int out_size) {
    const int*   inputs = (const int*)d_in[0];
    const float* emb = (const float*)d_in[1];
    const float* Wxr = (const float*)d_in[2];
    const float* Whr = (const float*)d_in[3];
    const float* br  = (const float*)d_in[4];
    const float* Wxz = (const float*)d_in[5];
    const float* Whz = (const float*)d_in[6];
    const float* bz  = (const float*)d_in[7];
    const float* Wxc = (const float*)d_in[8];
    const float* Whc = (const float*)d_in[9];
    const float* bc  = (const float*)d_in[10];
    const float* Whq = (const float*)d_in[11];
    const float* bq  = (const float*)d_in[12];
    float* out = (float*)d_out;

    reset_kernel<<<1, 256>>>();
    dim3 pg(48, 512);
    proj_kernel<<<pg, 256>>>(inputs, emb, Wxr, Wxz, Wxc, br, bz, bc);
    gru_kernel<<<NBLK, GTHR>>>(Whr, Whz, Whc);
    out_kernel<<<64, 256>>>(Whq, bq, out);
}